// round 5
// baseline (speedup 1.0000x reference)
#include <cuda_runtime.h>
#include <math.h>

// Problem constants
#define BB 8
#define HH 256
#define WW2 256
#define CDIM 96
#define NHEAD 4
#define HD 24
#define WS 8
#define NTOK 64
#define SHIFT 4
#define NWIN 8192     // B * 32 * 32
#define NPIX (BB*HH*WW2)

// ---- k_attn smem layout (floats) ----
#define YS 97
#define QS 289
#define SS 65
#define SMEM1_FLOATS (64*YS + 64*QS + 900)
#define SMEM1 (SMEM1_FLOATS*4)

// ---- k_mlp smem layout (floats) ----
#define MROWS 128
#define SXS 96
#define SNS 100
#define STS 68
#define SW1S 64
#define SW2S 96
#define SMEM2_FLOATS (MROWS*SXS + MROWS*SNS + MROWS*STS + 96*SW1S + 64*SW2S)
#define SMEM2 (SMEM2_FLOATS*4)

// scratch: x1 = shortcut + attention branch
static __device__ float g_x1[(size_t)BB*HH*WW2*CDIM];

// ---------------------------------------------------------------------------
// Kernel 1: per-window  LN1 + shift + QKV + attention + proj + residual
// ---------------------------------------------------------------------------
__global__ __launch_bounds__(256, 2) void k_attn(
    const float* __restrict__ x,
    const float* __restrict__ n1g, const float* __restrict__ n1b,
    const float* __restrict__ qkvw, const float* __restrict__ qkvb,
    const float* __restrict__ relb,
    const float* __restrict__ pw,  const float* __restrict__ pb)
{
    extern __shared__ float sm[];
    float* sy    = sm;                 // 64 x YS (LN'd; later attn out)
    float* ss    = sm;                 // 64 x SS (scores; aliases sy, disjoint lifetime)
    float* sq    = sm + 64*YS;         // 64 x QS (qkv 288 cols)
    float* sbias = sq + 64*QS;         // 4 x 225 clipped rel-bias LUT

    const int t   = threadIdx.x;
    const int win = blockIdx.x;
    const int b   = win >> 10;
    const int wr  = win & 1023;
    const int wh  = wr >> 5;
    const int ww  = wr & 31;

    // ---- clipped rel-bias LUT ----
    for (int e = t; e < 900; e += 256) {
        const int h = e / 225, idx = e - h*225;
        float bv = relb[idx*NHEAD + h];
        sbias[e] = fminf(fmaxf(bv, -5.f), 5.f);
    }

    // ---- LN1 with cyclic-shift gather: 4 lanes per token ----
    {
        const int n = t >> 2, q = t & 3;
        const int i = n >> 3, j = n & 7;
        const int h0 = (wh*8 + i + SHIFT) & 255;
        const int w0 = (ww*8 + j + SHIFT) & 255;
        const float* xp = x + (((size_t)b*HH + h0)*WW2 + w0)*CDIM;
        float v[24];
        float s1 = 0.f, s2 = 0.f;
#pragma unroll
        for (int k = 0; k < 24; k++) {
            float vv = xp[q + 4*k];
            v[k] = vv; s1 += vv; s2 += vv*vv;
        }
        s1 += __shfl_xor_sync(0xffffffffu, s1, 1);
        s2 += __shfl_xor_sync(0xffffffffu, s2, 1);
        s1 += __shfl_xor_sync(0xffffffffu, s1, 2);
        s2 += __shfl_xor_sync(0xffffffffu, s2, 2);
        const float mean = s1 * (1.f/96.f);
        const float var  = s2 * (1.f/96.f) - mean*mean;
        const float rstd = rsqrtf(var + 1e-5f);
#pragma unroll
        for (int k = 0; k < 24; k++) {
            const int c = q + 4*k;
            sy[n*YS + c] = (v[k]-mean)*rstd*n1g[c] + n1b[c];
        }
    }
    __syncthreads();

    const int tx = t & 15, ty = t >> 4;

    // ---- QKV GEMM: (64x96)@(96x288) + bias -> sq.  3 passes x 96 cols,
    //      per-thread tile 4 rows x 6 cols (16*6 = 96, no guards) ----
    for (int co0 = 0; co0 < 288; co0 += 96) {
        float acc[4][6];
#pragma unroll
        for (int rr = 0; rr < 4; rr++)
#pragma unroll
            for (int cc = 0; cc < 6; cc++) acc[rr][cc] = 0.f;
#pragma unroll 4
        for (int ci = 0; ci < 96; ci++) {
            float a[4], w[6];
#pragma unroll
            for (int rr = 0; rr < 4; rr++) a[rr] = sy[(ty + 16*rr)*YS + ci];
#pragma unroll
            for (int cc = 0; cc < 6; cc++) w[cc] = qkvw[ci*288 + co0 + tx + 16*cc];
#pragma unroll
            for (int rr = 0; rr < 4; rr++)
#pragma unroll
                for (int cc = 0; cc < 6; cc++) acc[rr][cc] = fmaf(a[rr], w[cc], acc[rr][cc]);
        }
#pragma unroll
        for (int rr = 0; rr < 4; rr++)
#pragma unroll
            for (int cc = 0; cc < 6; cc++) {
                const int c = co0 + tx + 16*cc;
                sq[(ty + 16*rr)*QS + c] = acc[rr][cc] + qkvb[c];
            }
    }
    __syncthreads();
    // sy's LN contents are dead from here; ss (scores) reuses that space.

    const float SCALE = rsqrtf((float)HD);
    const bool edgeH = (wh == 31), edgeW = (ww == 31);

    float oreg[NHEAD][6];   // attention output accumulators, in registers

    for (int h = 0; h < NHEAD; h++) {
        const int qo = h*HD, ko = 96 + h*HD, vo = 192 + h*HD;

        // scores (64x64): per-thread 4x4 tile
        {
            float acc[4][4];
#pragma unroll
            for (int rr = 0; rr < 4; rr++)
#pragma unroll
                for (int cc = 0; cc < 4; cc++) acc[rr][cc] = 0.f;
#pragma unroll 4
            for (int d = 0; d < HD; d++) {
                float a[4], k2[4];
#pragma unroll
                for (int rr = 0; rr < 4; rr++) a[rr]  = sq[(ty + 16*rr)*QS + qo + d];
#pragma unroll
                for (int cc = 0; cc < 4; cc++) k2[cc] = sq[(tx + 16*cc)*QS + ko + d];
#pragma unroll
                for (int rr = 0; rr < 4; rr++)
#pragma unroll
                    for (int cc = 0; cc < 4; cc++) acc[rr][cc] = fmaf(a[rr], k2[cc], acc[rr][cc]);
            }
#pragma unroll
            for (int rr = 0; rr < 4; rr++) {
                const int n1 = ty + 16*rr;
                const int i1 = n1 >> 3, j1 = n1 & 7;
                const int r1 = (edgeH ? ((i1 < 4) ? 1 : 2) : 0)*3 + (edgeW ? ((j1 < 4) ? 1 : 2) : 0);
#pragma unroll
                for (int cc = 0; cc < 4; cc++) {
                    const int n2 = tx + 16*cc;
                    const int i2 = n2 >> 3, j2 = n2 & 7;
                    const int r2 = (edgeH ? ((i2 < 4) ? 1 : 2) : 0)*3 + (edgeW ? ((j2 < 4) ? 1 : 2) : 0);
                    const int di = i1 - i2 + 7, dj = j1 - j2 + 7;
                    float bias = sbias[h*225 + di*15 + dj];
                    float v = acc[rr][cc]*SCALE + ((r1 == r2) ? 0.f : -1e9f) + bias;
                    v = fminf(fmaxf(v, -10.f), 10.f);
                    ss[n1*SS + n2] = v;
                }
            }
        }
        __syncthreads();

        // softmax per row (quad of lanes per row, within one warp)
        {
            const int rn = t >> 2, rq = t & 3;
            float m = -1e30f;
#pragma unroll
            for (int k = 0; k < 16; k++) m = fmaxf(m, ss[rn*SS + rq*16 + k]);
            m = fmaxf(m, __shfl_xor_sync(0xffffffffu, m, 1));
            m = fmaxf(m, __shfl_xor_sync(0xffffffffu, m, 2));
            float sum = 0.f;
#pragma unroll
            for (int k = 0; k < 16; k++) {
                float e = __expf(ss[rn*SS + rq*16 + k] - m);
                ss[rn*SS + rq*16 + k] = e;
                sum += e;
            }
            sum += __shfl_xor_sync(0xffffffffu, sum, 1);
            sum += __shfl_xor_sync(0xffffffffu, sum, 2);
            const float inv = 1.f / sum;
#pragma unroll
            for (int k = 0; k < 16; k++) ss[rn*SS + rq*16 + k] *= inv;
            __syncwarp();
        }

        // AV -> registers (thread t: row t>>2, 6 head-dims starting (t&3)*6)
        {
            const int dn = t >> 2, dq = t & 3;
            float acc[6];
#pragma unroll
            for (int k = 0; k < 6; k++) acc[k] = 0.f;
#pragma unroll 4
            for (int j = 0; j < 64; j++) {
                const float sv = ss[dn*SS + j];
#pragma unroll
                for (int k = 0; k < 6; k++)
                    acc[k] = fmaf(sv, sq[j*QS + vo + dq*6 + k], acc[k]);
            }
#pragma unroll
            for (int k = 0; k < 6; k++) oreg[h][k] = acc[k];
        }
        __syncthreads();
    }

    // write o (registers) -> sy, overwriting the dead score buffer
    {
        const int dn = t >> 2, dq = t & 3;
#pragma unroll
        for (int h = 0; h < NHEAD; h++)
#pragma unroll
            for (int k = 0; k < 6; k++)
                sy[dn*YS + h*HD + dq*6 + k] = oreg[h][k];
    }
    __syncthreads();

    // ---- proj (64x96)@(96x96) + un-shift + residual -> g_x1.
    //      per-thread 4 rows x 6 cols: covers all 96 cols, no guards ----
    {
        float acc[4][6];
#pragma unroll
        for (int rr = 0; rr < 4; rr++)
#pragma unroll
            for (int cc = 0; cc < 6; cc++) acc[rr][cc] = 0.f;
#pragma unroll 4
        for (int k = 0; k < 96; k++) {
            float a[4], w[6];
#pragma unroll
            for (int rr = 0; rr < 4; rr++) a[rr] = sy[(ty + 16*rr)*YS + k];
#pragma unroll
            for (int cc = 0; cc < 6; cc++) w[cc] = pw[k*96 + tx + 16*cc];
#pragma unroll
            for (int rr = 0; rr < 4; rr++)
#pragma unroll
                for (int cc = 0; cc < 6; cc++) acc[rr][cc] = fmaf(a[rr], w[cc], acc[rr][cc]);
        }
#pragma unroll
        for (int rr = 0; rr < 4; rr++) {
            const int n = ty + 16*rr;
            const int i = n >> 3, j = n & 7;
            const int h1 = (wh*8 + i + SHIFT) & 255;
            const int w1 = (ww*8 + j + SHIFT) & 255;
            const size_t base = (((size_t)b*HH + h1)*WW2 + w1)*CDIM;
#pragma unroll
            for (int cc = 0; cc < 6; cc++) {
                const int c = tx + 16*cc;
                g_x1[base + c] = x[base + c] + acc[rr][cc] + pb[c];
            }
        }
    }
}

// ---------------------------------------------------------------------------
// Kernel 2: 128 pixels/block  LN2 + MLP (96->384 GELU 384->96) + residual
// Chunk-fused: per 64 hidden cols, GEMM1+GELU -> smem chunk -> partial GEMM2
// into persistent register accumulators. Weights staged through smem.
// ---------------------------------------------------------------------------
__global__ __launch_bounds__(256, 1) void k_mlp(
    const float* __restrict__ n2g, const float* __restrict__ n2b,
    const float* __restrict__ w1,  const float* __restrict__ b1,
    const float* __restrict__ w2,  const float* __restrict__ b2,
    float* __restrict__ out)
{
    extern __shared__ float sm[];
    float* sx  = sm;                       // MROWS x 96  raw x1 (residual)
    float* sn  = sx  + MROWS*SXS;          // MROWS x 100 LN'd
    float* st  = sn  + MROWS*SNS;          // MROWS x 68  hidden chunk (GELU'd)
    float* sw1 = st  + MROWS*STS;          // 96 x 64     staged w1 chunk
    float* sw2 = sw1 + 96*SW1S;            // 64 x 96     staged w2 chunk

    const int t  = threadIdx.x;
    const size_t p0 = (size_t)blockIdx.x * MROWS;

    // load 128 consecutive pixels (float4)
    {
        const float4* src = (const float4*)(g_x1 + p0*CDIM);
        float4* dst = (float4*)sx;
        for (int e = t; e < MROWS*CDIM/4; e += 256) dst[e] = src[e];
    }
    __syncthreads();

    // LN2: 2 lanes per row, 48 contiguous cols each
    {
        const int n = t >> 1, q = t & 1;
        const float* row = sx + n*SXS + q*48;
        float s1 = 0.f, s2 = 0.f;
#pragma unroll
        for (int k = 0; k < 12; k++) {
            float4 v = ((const float4*)row)[k];
            s1 += v.x+v.y+v.z+v.w;
            s2 += v.x*v.x+v.y*v.y+v.z*v.z+v.w*v.w;
        }
        s1 += __shfl_xor_sync(0xffffffffu, s1, 1);
        s2 += __shfl_xor_sync(0xffffffffu, s2, 1);
        const float mean = s1 * (1.f/96.f);
        const float var  = s2 * (1.f/96.f) - mean*mean;
        const float rstd = rsqrtf(var + 1e-5f);
        float* drow = sn + n*SNS + q*48;
        const float4* gg = (const float4*)(n2g + q*48);
        const float4* bb = (const float4*)(n2b + q*48);
#pragma unroll
        for (int k = 0; k < 12; k++) {
            float4 v = ((const float4*)row)[k];
            float4 g = gg[k], b = bb[k], o;
            o.x = (v.x-mean)*rstd*g.x + b.x;
            o.y = (v.y-mean)*rstd*g.y + b.y;
            o.z = (v.z-mean)*rstd*g.z + b.z;
            o.w = (v.w-mean)*rstd*g.w + b.w;
            ((float4*)drow)[k] = o;
        }
    }
    __syncthreads();

    const int tx = t & 15, ty = t >> 4;

    // persistent output accumulators: 8 rows x 6 cols per thread
    float acc2[8][6];
#pragma unroll
    for (int rr = 0; rr < 8; rr++)
#pragma unroll
        for (int cc = 0; cc < 6; cc++) acc2[rr][cc] = 0.f;

    for (int chunk = 0; chunk < 6; chunk++) {
        const int co0 = chunk * 64;

        // stage w1 chunk (96 x 64) and w2 chunk (64 x 96), float4
        {
            float4* d1 = (float4*)sw1;
            for (int e = t; e < 96*64/4; e += 256) {
                const int ci = e >> 4, c4 = e & 15;
                const float4* s1p = (const float4*)(w1 + ci*384 + co0);
                d1[ci*16 + c4] = s1p[c4];
            }
            float4* d2 = (float4*)sw2;
            const float4* s2p = (const float4*)(w2 + co0*96);
            for (int e = t; e < 64*96/4; e += 256) d2[e] = s2p[e];
        }
        __syncthreads();

        // GEMM1: (128x96)@(96x64) + b1, GELU -> st
        {
            float acc1[8][4];
#pragma unroll
            for (int rr = 0; rr < 8; rr++)
#pragma unroll
                for (int cc = 0; cc < 4; cc++) acc1[rr][cc] = 0.f;

            for (int ci = 0; ci < 96; ci += 4) {
                float4 a4[8], w4[4];
#pragma unroll
                for (int rr = 0; rr < 8; rr++)
                    a4[rr] = *(const float4*)(sn + (ty + 16*rr)*SNS + ci);
#pragma unroll
                for (int j = 0; j < 4; j++)
                    w4[j] = *(const float4*)(sw1 + (ci + j)*SW1S + tx*4);
#pragma unroll
                for (int rr = 0; rr < 8; rr++) {
#pragma unroll
                    for (int j = 0; j < 4; j++) {
                        const float av = (j==0)?a4[rr].x:(j==1)?a4[rr].y:(j==2)?a4[rr].z:a4[rr].w;
                        acc1[rr][0] = fmaf(av, w4[j].x, acc1[rr][0]);
                        acc1[rr][1] = fmaf(av, w4[j].y, acc1[rr][1]);
                        acc1[rr][2] = fmaf(av, w4[j].z, acc1[rr][2]);
                        acc1[rr][3] = fmaf(av, w4[j].w, acc1[rr][3]);
                    }
                }
            }
            const float4 b1v = *(const float4*)(b1 + co0 + tx*4);
#pragma unroll
            for (int rr = 0; rr < 8; rr++) {
                float v0 = acc1[rr][0] + b1v.x;
                float v1 = acc1[rr][1] + b1v.y;
                float v2 = acc1[rr][2] + b1v.z;
                float v3 = acc1[rr][3] + b1v.w;
                v0 = 0.5f*v0*(1.f + erff(v0*0.7071067811865476f));
                v1 = 0.5f*v1*(1.f + erff(v1*0.7071067811865476f));
                v2 = 0.5f*v2*(1.f + erff(v2*0.7071067811865476f));
                v3 = 0.5f*v3*(1.f + erff(v3*0.7071067811865476f));
                float4 o4 = make_float4(v0, v1, v2, v3);
                *(float4*)(st + (ty + 16*rr)*STS + tx*4) = o4;
            }
        }
        __syncthreads();

        // GEMM2 partial: (128x64)@(64x96) accumulated into acc2
        for (int k = 0; k < 64; k++) {
            float a[8], w[6];
#pragma unroll
            for (int rr = 0; rr < 8; rr++) a[rr] = st[(ty + 16*rr)*STS + k];
#pragma unroll
            for (int cc = 0; cc < 6; cc++) w[cc] = sw2[k*SW2S + tx + 16*cc];
#pragma unroll
            for (int rr = 0; rr < 8; rr++)
#pragma unroll
                for (int cc = 0; cc < 6; cc++) acc2[rr][cc] = fmaf(a[rr], w[cc], acc2[rr][cc]);
        }
        __syncthreads();
    }

    // store: out = x1 + mlp + b2
#pragma unroll
    for (int cc = 0; cc < 6; cc++) {
        const int c = tx + 16*cc;
        const float b2v = b2[c];
#pragma unroll
        for (int rr = 0; rr < 8; rr++) {
            const int r = ty + 16*rr;
            out[(p0 + r)*CDIM + c] = sx[r*SXS + c] + acc2[rr][cc] + b2v;
        }
    }
}

// ---------------------------------------------------------------------------
extern "C" void kernel_launch(void* const* d_in, const int* in_sizes, int n_in,
                              void* d_out, int out_size)
{
    const float* x    = (const float*)d_in[0];
    const float* n1g  = (const float*)d_in[1];
    const float* n1b  = (const float*)d_in[2];
    const float* qkvw = (const float*)d_in[3];
    const float* qkvb = (const float*)d_in[4];
    const float* relb = (const float*)d_in[5];
    const float* pw   = (const float*)d_in[6];
    const float* pb   = (const float*)d_in[7];
    const float* n2g  = (const float*)d_in[8];
    const float* n2b  = (const float*)d_in[9];
    const float* w1   = (const float*)d_in[10];
    const float* b1   = (const float*)d_in[11];
    const float* w2   = (const float*)d_in[12];
    const float* b2   = (const float*)d_in[13];
    float* out = (float*)d_out;

    cudaFuncSetAttribute(k_attn, cudaFuncAttributeMaxDynamicSharedMemorySize, SMEM1);
    cudaFuncSetAttribute(k_mlp,  cudaFuncAttributeMaxDynamicSharedMemorySize, SMEM2);

    k_attn<<<NWIN, 256, SMEM1>>>(x, n1g, n1b, qkvw, qkvb, relb, pw, pb);
    k_mlp<<<NPIX/MROWS, 256, SMEM2>>>(n2g, n2b, w1, b1, w2, b2, out);
}

// round 9
// speedup vs baseline: 1.7435x; 1.7435x over previous
#include <cuda_runtime.h>
#include <cuda_bf16.h>
#include <math.h>
#include <stdint.h>

// Problem constants
#define BB 8
#define HH 256
#define WW2 256
#define CDIM 96
#define NHEAD 4
#define HD 24
#define WS 8
#define NTOK 64
#define SHIFT 4
#define NWIN 8192     // B * 32 * 32
#define NPIX (BB*HH*WW2)

// ---- k_attn smem layout (floats) ----
#define YS 97
#define QS 289
#define SS 65
#define SMEM1_FLOATS (64*YS + 64*QS + 900)
#define SMEM1 (SMEM1_FLOATS*4)

// scratch: x1 = shortcut + attention branch
static __device__ float g_x1[(size_t)BB*HH*WW2*CDIM];

// ===========================================================================
// k_mlp_mma smem layout (u32 units)
//   sb1  [0,384)        b1
//   sb2  [384,480)      b2
//   A32  [512, +128*52) LN2'd activations, bf16x2 pairs, row stride 52
//   H32  [.., +128*36)  GELU'd hidden chunk, row stride 36
//   W1s  [.., +64*52)   W1 chunk as [n][k] bf16x2 pairs
//   W2s  [.., +96*36)   W2 chunk as [n][k] bf16x2 pairs
// ===========================================================================
#define SB1_O  0
#define SB2_O  384
#define A_O    512
#define H_O    (A_O + 128*52)     // 7168
#define W1_O   (H_O + 128*36)     // 11776
#define W2_O   (W1_O + 64*52)     // 15104
#define SMEM_M_U32 (W2_O + 96*36) // 18560
#define SMEM_M (SMEM_M_U32*4)     // 74240 bytes

// bf16 mma m16n8k16 (portable PTX, runs on HMMA)
__device__ __forceinline__ void mma_bf16(float* d, uint32_t a0, uint32_t a1,
                                         uint32_t a2, uint32_t a3,
                                         uint32_t b0, uint32_t b1) {
    asm volatile(
        "mma.sync.aligned.m16n8k16.row.col.f32.bf16.bf16.f32 "
        "{%0,%1,%2,%3}, {%4,%5,%6,%7}, {%8,%9}, {%0,%1,%2,%3};"
        : "+f"(d[0]), "+f"(d[1]), "+f"(d[2]), "+f"(d[3])
        : "r"(a0), "r"(a1), "r"(a2), "r"(a3), "r"(b0), "r"(b1));
}

__device__ __forceinline__ uint32_t pack_bf16(float lo, float hi) {
    __nv_bfloat162 v = __floats2bfloat162_rn(lo, hi);
    return *(uint32_t*)&v;
}

// ---------------------------------------------------------------------------
// Kernel 1: per-window  LN1 + shift + QKV + attention + proj + residual
// (unchanged — known good)
// ---------------------------------------------------------------------------
__global__ __launch_bounds__(256, 2) void k_attn(
    const float* __restrict__ x,
    const float* __restrict__ n1g, const float* __restrict__ n1b,
    const float* __restrict__ qkvw, const float* __restrict__ qkvb,
    const float* __restrict__ relb,
    const float* __restrict__ pw,  const float* __restrict__ pb)
{
    extern __shared__ float sm[];
    float* sy    = sm;
    float* ss    = sm;
    float* sq    = sm + 64*YS;
    float* sbias = sq + 64*QS;

    const int t   = threadIdx.x;
    const int win = blockIdx.x;
    const int b   = win >> 10;
    const int wr  = win & 1023;
    const int wh  = wr >> 5;
    const int ww  = wr & 31;

    for (int e = t; e < 900; e += 256) {
        const int h = e / 225, idx = e - h*225;
        float bv = relb[idx*NHEAD + h];
        sbias[e] = fminf(fmaxf(bv, -5.f), 5.f);
    }

    {
        const int n = t >> 2, q = t & 3;
        const int i = n >> 3, j = n & 7;
        const int h0 = (wh*8 + i + SHIFT) & 255;
        const int w0 = (ww*8 + j + SHIFT) & 255;
        const float* xp = x + (((size_t)b*HH + h0)*WW2 + w0)*CDIM;
        float v[24];
        float s1 = 0.f, s2 = 0.f;
#pragma unroll
        for (int k = 0; k < 24; k++) {
            float vv = xp[q + 4*k];
            v[k] = vv; s1 += vv; s2 += vv*vv;
        }
        s1 += __shfl_xor_sync(0xffffffffu, s1, 1);
        s2 += __shfl_xor_sync(0xffffffffu, s2, 1);
        s1 += __shfl_xor_sync(0xffffffffu, s1, 2);
        s2 += __shfl_xor_sync(0xffffffffu, s2, 2);
        const float mean = s1 * (1.f/96.f);
        const float var  = s2 * (1.f/96.f) - mean*mean;
        const float rstd = rsqrtf(var + 1e-5f);
#pragma unroll
        for (int k = 0; k < 24; k++) {
            const int c = q + 4*k;
            sy[n*YS + c] = (v[k]-mean)*rstd*n1g[c] + n1b[c];
        }
    }
    __syncthreads();

    const int tx = t & 15, ty = t >> 4;

    for (int co0 = 0; co0 < 288; co0 += 96) {
        float acc[4][6];
#pragma unroll
        for (int rr = 0; rr < 4; rr++)
#pragma unroll
            for (int cc = 0; cc < 6; cc++) acc[rr][cc] = 0.f;
#pragma unroll 4
        for (int ci = 0; ci < 96; ci++) {
            float a[4], w[6];
#pragma unroll
            for (int rr = 0; rr < 4; rr++) a[rr] = sy[(ty + 16*rr)*YS + ci];
#pragma unroll
            for (int cc = 0; cc < 6; cc++) w[cc] = qkvw[ci*288 + co0 + tx + 16*cc];
#pragma unroll
            for (int rr = 0; rr < 4; rr++)
#pragma unroll
                for (int cc = 0; cc < 6; cc++) acc[rr][cc] = fmaf(a[rr], w[cc], acc[rr][cc]);
        }
#pragma unroll
        for (int rr = 0; rr < 4; rr++)
#pragma unroll
            for (int cc = 0; cc < 6; cc++) {
                const int c = co0 + tx + 16*cc;
                sq[(ty + 16*rr)*QS + c] = acc[rr][cc] + qkvb[c];
            }
    }
    __syncthreads();

    const float SCALE = rsqrtf((float)HD);
    const bool edgeH = (wh == 31), edgeW = (ww == 31);

    float oreg[NHEAD][6];

    for (int h = 0; h < NHEAD; h++) {
        const int qo = h*HD, ko = 96 + h*HD, vo = 192 + h*HD;
        {
            float acc[4][4];
#pragma unroll
            for (int rr = 0; rr < 4; rr++)
#pragma unroll
                for (int cc = 0; cc < 4; cc++) acc[rr][cc] = 0.f;
#pragma unroll 4
            for (int d = 0; d < HD; d++) {
                float a[4], k2[4];
#pragma unroll
                for (int rr = 0; rr < 4; rr++) a[rr]  = sq[(ty + 16*rr)*QS + qo + d];
#pragma unroll
                for (int cc = 0; cc < 4; cc++) k2[cc] = sq[(tx + 16*cc)*QS + ko + d];
#pragma unroll
                for (int rr = 0; rr < 4; rr++)
#pragma unroll
                    for (int cc = 0; cc < 4; cc++) acc[rr][cc] = fmaf(a[rr], k2[cc], acc[rr][cc]);
            }
#pragma unroll
            for (int rr = 0; rr < 4; rr++) {
                const int n1 = ty + 16*rr;
                const int i1 = n1 >> 3, j1 = n1 & 7;
                const int r1 = (edgeH ? ((i1 < 4) ? 1 : 2) : 0)*3 + (edgeW ? ((j1 < 4) ? 1 : 2) : 0);
#pragma unroll
                for (int cc = 0; cc < 4; cc++) {
                    const int n2 = tx + 16*cc;
                    const int i2 = n2 >> 3, j2 = n2 & 7;
                    const int r2 = (edgeH ? ((i2 < 4) ? 1 : 2) : 0)*3 + (edgeW ? ((j2 < 4) ? 1 : 2) : 0);
                    const int di = i1 - i2 + 7, dj = j1 - j2 + 7;
                    float bias = sbias[h*225 + di*15 + dj];
                    float v = acc[rr][cc]*SCALE + ((r1 == r2) ? 0.f : -1e9f) + bias;
                    v = fminf(fmaxf(v, -10.f), 10.f);
                    ss[n1*SS + n2] = v;
                }
            }
        }
        __syncthreads();

        {
            const int rn = t >> 2, rq = t & 3;
            float m = -1e30f;
#pragma unroll
            for (int k = 0; k < 16; k++) m = fmaxf(m, ss[rn*SS + rq*16 + k]);
            m = fmaxf(m, __shfl_xor_sync(0xffffffffu, m, 1));
            m = fmaxf(m, __shfl_xor_sync(0xffffffffu, m, 2));
            float sum = 0.f;
#pragma unroll
            for (int k = 0; k < 16; k++) {
                float e = __expf(ss[rn*SS + rq*16 + k] - m);
                ss[rn*SS + rq*16 + k] = e;
                sum += e;
            }
            sum += __shfl_xor_sync(0xffffffffu, sum, 1);
            sum += __shfl_xor_sync(0xffffffffu, sum, 2);
            const float inv = 1.f / sum;
#pragma unroll
            for (int k = 0; k < 16; k++) ss[rn*SS + rq*16 + k] *= inv;
            __syncwarp();
        }

        {
            const int dn = t >> 2, dq = t & 3;
            float acc[6];
#pragma unroll
            for (int k = 0; k < 6; k++) acc[k] = 0.f;
#pragma unroll 4
            for (int j = 0; j < 64; j++) {
                const float sv = ss[dn*SS + j];
#pragma unroll
                for (int k = 0; k < 6; k++)
                    acc[k] = fmaf(sv, sq[j*QS + vo + dq*6 + k], acc[k]);
            }
#pragma unroll
            for (int k = 0; k < 6; k++) oreg[h][k] = acc[k];
        }
        __syncthreads();
    }

    {
        const int dn = t >> 2, dq = t & 3;
#pragma unroll
        for (int h = 0; h < NHEAD; h++)
#pragma unroll
            for (int k = 0; k < 6; k++)
                sy[dn*YS + h*HD + dq*6 + k] = oreg[h][k];
    }
    __syncthreads();

    {
        float acc[4][6];
#pragma unroll
        for (int rr = 0; rr < 4; rr++)
#pragma unroll
            for (int cc = 0; cc < 6; cc++) acc[rr][cc] = 0.f;
#pragma unroll 4
        for (int k = 0; k < 96; k++) {
            float a[4], w[6];
#pragma unroll
            for (int rr = 0; rr < 4; rr++) a[rr] = sy[(ty + 16*rr)*YS + k];
#pragma unroll
            for (int cc = 0; cc < 6; cc++) w[cc] = pw[k*96 + tx + 16*cc];
#pragma unroll
            for (int rr = 0; rr < 4; rr++)
#pragma unroll
                for (int cc = 0; cc < 6; cc++) acc[rr][cc] = fmaf(a[rr], w[cc], acc[rr][cc]);
        }
#pragma unroll
        for (int rr = 0; rr < 4; rr++) {
            const int n = ty + 16*rr;
            const int i = n >> 3, j = n & 7;
            const int h1 = (wh*8 + i + SHIFT) & 255;
            const int w1 = (ww*8 + j + SHIFT) & 255;
            const size_t base = (((size_t)b*HH + h1)*WW2 + w1)*CDIM;
#pragma unroll
            for (int cc = 0; cc < 6; cc++) {
                const int c = tx + 16*cc;
                g_x1[base + c] = x[base + c] + acc[rr][cc] + pb[c];
            }
        }
    }
}

// ---------------------------------------------------------------------------
// Kernel 2 (HMMA): 128 pixels/block  LN2 + MLP + residual via mma.sync bf16
// Per 64-col hidden chunk: GEMM1 (A[128x96]@W1c^T) +b1 -> GELU -> H bf16,
// GEMM2 accumulates D2[128x96] += H @ W2c^T in registers across 6 chunks.
// Each warp owns a 16-row slab; H handoff needs only __syncwarp().
// ---------------------------------------------------------------------------
__global__ __launch_bounds__(256, 2) void k_mlp_mma(
    const float* __restrict__ n2g, const float* __restrict__ n2b,
    const float* __restrict__ w1,  const float* __restrict__ b1,
    const float* __restrict__ w2,  const float* __restrict__ b2,
    float* __restrict__ out)
{
    extern __shared__ uint32_t smu[];
    float*    sb1 = (float*)(smu + SB1_O);
    float*    sb2 = (float*)(smu + SB2_O);
    uint32_t* A32 = smu + A_O;
    uint32_t* H32 = smu + H_O;
    uint32_t* W1s = smu + W1_O;
    uint32_t* W2s = smu + W2_O;

    const int t    = threadIdx.x;
    const int wid  = t >> 5;
    const int lane = t & 31;
    const int g    = lane >> 2;     // group id (row within fragment)
    const int tig  = lane & 3;      // thread in group
    const int r0   = wid * 16;      // warp's row slab
    const size_t p0 = (size_t)blockIdx.x * 128;

    // stage biases
    for (int i = t; i < 384; i += 256) sb1[i] = b1[i];
    if (t < 96) sb2[t] = b2[t];

    // ---- LN2 -> A32 (bf16x2 pairs, row stride 52) ----
    {
        const int row = t >> 1, q = t & 1;
        const float* xr = g_x1 + (p0 + row)*96 + q*48;
        float v[48];
        float s1 = 0.f, s2 = 0.f;
#pragma unroll
        for (int k = 0; k < 12; k++) {
            float4 f = ((const float4*)xr)[k];
            v[4*k+0]=f.x; v[4*k+1]=f.y; v[4*k+2]=f.z; v[4*k+3]=f.w;
            s1 += f.x+f.y+f.z+f.w;
            s2 += f.x*f.x+f.y*f.y+f.z*f.z+f.w*f.w;
        }
        s1 += __shfl_xor_sync(0xffffffffu, s1, 1);
        s2 += __shfl_xor_sync(0xffffffffu, s2, 1);
        const float mean = s1 * (1.f/96.f);
        const float var  = s2 * (1.f/96.f) - mean*mean;
        const float rstd = rsqrtf(var + 1e-5f);
#pragma unroll
        for (int k = 0; k < 24; k++) {
            const int c = q*48 + 2*k;
            float a0 = (v[2*k]   - mean)*rstd*n2g[c]   + n2b[c];
            float a1 = (v[2*k+1] - mean)*rstd*n2g[c+1] + n2b[c+1];
            A32[row*52 + q*24 + k] = pack_bf16(a0, a1);
        }
    }

    // persistent GEMM2 accumulators: 12 n-tiles x 4 regs (rows g,g+8 / cols 2tig,+1)
    float d2[12][4];
#pragma unroll
    for (int nt = 0; nt < 12; nt++)
#pragma unroll
        for (int i = 0; i < 4; i++) d2[nt][i] = 0.f;

    for (int c = 0; c < 6; c++) {
        const int co0 = c*64;
        __syncthreads();   // A ready (1st iter) / previous chunk's W,H consumed

        // ---- stage W1c as [n][k]: W1s[n*52 + kp] = (w1[2kp][co0+n], w1[2kp+1][co0+n]) ----
#pragma unroll
        for (int i = 0; i < 12; i++) {
            const int p = t + 256*i;            // p < 3072
            const int n = p & 63, kp = p >> 6;  // kp < 48
            float f0 = w1[(size_t)(2*kp)*384   + co0 + n];
            float f1 = w1[(size_t)(2*kp+1)*384 + co0 + n];
            W1s[n*52 + kp] = pack_bf16(f0, f1);
        }
        // ---- stage W2c as [n][k]: W2s[n*36 + kp] = (w2[(co0+2kp)][n], w2[(co0+2kp+1)][n]) ----
#pragma unroll
        for (int i = 0; i < 12; i++) {
            const int p = t + 256*i;            // p < 3072
            const int n = p % 96, kp = p / 96;  // kp < 32
            float f0 = w2[(size_t)(co0+2*kp)*96   + n];
            float f1 = w2[(size_t)(co0+2*kp+1)*96 + n];
            W2s[n*36 + kp] = pack_bf16(f0, f1);
        }
        __syncthreads();

        // ---- GEMM1: d1[16x64] = A[16x96] @ W1c^T ----
        float d1[8][4];
#pragma unroll
        for (int nt = 0; nt < 8; nt++)
#pragma unroll
            for (int i = 0; i < 4; i++) d1[nt][i] = 0.f;

#pragma unroll
        for (int s = 0; s < 6; s++) {
            const int kp0 = 8*s;
            uint32_t a0 = A32[(r0+g)*52   + kp0 + tig];
            uint32_t a1 = A32[(r0+g+8)*52 + kp0 + tig];
            uint32_t a2 = A32[(r0+g)*52   + kp0 + 4 + tig];
            uint32_t a3 = A32[(r0+g+8)*52 + kp0 + 4 + tig];
#pragma unroll
            for (int nt = 0; nt < 8; nt++) {
                const int n = nt*8 + g;
                uint32_t b0 = W1s[n*52 + kp0 + tig];
                uint32_t b1v = W1s[n*52 + kp0 + 4 + tig];
                mma_bf16(d1[nt], a0, a1, a2, a3, b0, b1v);
            }
        }

        // ---- epilogue1: +b1, GELU, -> H32 (bf16 pairs, stride 36) ----
#pragma unroll
        for (int nt = 0; nt < 8; nt++) {
            const int cn = nt*8 + 2*tig;
            const float bb0 = sb1[co0 + cn], bb1 = sb1[co0 + cn + 1];
            float v0 = d1[nt][0] + bb0, v1 = d1[nt][1] + bb1;
            float v2 = d1[nt][2] + bb0, v3 = d1[nt][3] + bb1;
            v0 = 0.5f*v0*(1.f + erff(v0*0.7071067811865476f));
            v1 = 0.5f*v1*(1.f + erff(v1*0.7071067811865476f));
            v2 = 0.5f*v2*(1.f + erff(v2*0.7071067811865476f));
            v3 = 0.5f*v3*(1.f + erff(v3*0.7071067811865476f));
            H32[(r0+g)*36   + nt*4 + tig] = pack_bf16(v0, v1);
            H32[(r0+g+8)*36 + nt*4 + tig] = pack_bf16(v2, v3);
        }
        __syncwarp();   // warp consumes only its own 16 H rows

        // ---- GEMM2: d2[16x96] += H[16x64] @ W2c^T ----
#pragma unroll
        for (int s = 0; s < 4; s++) {
            const int kp0 = 8*s;
            uint32_t a0 = H32[(r0+g)*36   + kp0 + tig];
            uint32_t a1 = H32[(r0+g+8)*36 + kp0 + tig];
            uint32_t a2 = H32[(r0+g)*36   + kp0 + 4 + tig];
            uint32_t a3 = H32[(r0+g+8)*36 + kp0 + 4 + tig];
#pragma unroll
            for (int nt = 0; nt < 12; nt++) {
                const int n = nt*8 + g;
                uint32_t b0 = W2s[n*36 + kp0 + tig];
                uint32_t b1v = W2s[n*36 + kp0 + 4 + tig];
                mma_bf16(d2[nt], a0, a1, a2, a3, b0, b1v);
            }
        }
    }

    // ---- epilogue2: out = x1 + d2 + b2 ----
#pragma unroll
    for (int nt = 0; nt < 12; nt++) {
        const int col = nt*8 + 2*tig;
        const float bb0 = sb2[col], bb1 = sb2[col + 1];
        const size_t i0 = (p0 + r0 + g)*96 + col;
        const size_t i1 = (p0 + r0 + g + 8)*96 + col;
        float2 x0 = *(const float2*)(g_x1 + i0);
        float2 x1v = *(const float2*)(g_x1 + i1);
        float2 o0, o1;
        o0.x = x0.x + d2[nt][0] + bb0;
        o0.y = x0.y + d2[nt][1] + bb1;
        o1.x = x1v.x + d2[nt][2] + bb0;
        o1.y = x1v.y + d2[nt][3] + bb1;
        *(float2*)(out + i0) = o0;
        *(float2*)(out + i1) = o1;
    }
}

// ---------------------------------------------------------------------------
extern "C" void kernel_launch(void* const* d_in, const int* in_sizes, int n_in,
                              void* d_out, int out_size)
{
    const float* x    = (const float*)d_in[0];
    const float* n1g  = (const float*)d_in[1];
    const float* n1b  = (const float*)d_in[2];
    const float* qkvw = (const float*)d_in[3];
    const float* qkvb = (const float*)d_in[4];
    const float* relb = (const float*)d_in[5];
    const float* pw   = (const float*)d_in[6];
    const float* pb   = (const float*)d_in[7];
    const float* n2g  = (const float*)d_in[8];
    const float* n2b  = (const float*)d_in[9];
    const float* w1   = (const float*)d_in[10];
    const float* b1   = (const float*)d_in[11];
    const float* w2   = (const float*)d_in[12];
    const float* b2   = (const float*)d_in[13];
    float* out = (float*)d_out;

    cudaFuncSetAttribute(k_attn,    cudaFuncAttributeMaxDynamicSharedMemorySize, SMEM1);
    cudaFuncSetAttribute(k_mlp_mma, cudaFuncAttributeMaxDynamicSharedMemorySize, SMEM_M);

    k_attn<<<NWIN, 256, SMEM1>>>(x, n1g, n1b, qkvw, qkvb, relb, pw, pb);
    k_mlp_mma<<<NPIX/128, 256, SMEM_M>>>(n2g, n2b, w1, b1, w2, b2, out);
}

// round 10
// speedup vs baseline: 4.4020x; 2.5248x over previous
#include <cuda_runtime.h>
#include <cuda_bf16.h>
#include <math.h>
#include <stdint.h>

// Problem constants
#define BB 8
#define HH 256
#define WW2 256
#define CDIM 96
#define NHEAD 4
#define HD 24
#define WS 8
#define NTOK 64
#define SHIFT 4
#define NWIN 8192     // B * 32 * 32
#define NPIX (BB*HH*WW2)

// scratch: x1 = shortcut + attention branch
static __device__ float g_x1[(size_t)BB*HH*WW2*CDIM];

// bf16 mma m16n8k16 (portable PTX, runs on HMMA)
__device__ __forceinline__ void mma_bf16(float* d, uint32_t a0, uint32_t a1,
                                         uint32_t a2, uint32_t a3,
                                         uint32_t b0, uint32_t b1) {
    asm volatile(
        "mma.sync.aligned.m16n8k16.row.col.f32.bf16.bf16.f32 "
        "{%0,%1,%2,%3}, {%4,%5,%6,%7}, {%8,%9}, {%0,%1,%2,%3};"
        : "+f"(d[0]), "+f"(d[1]), "+f"(d[2]), "+f"(d[3])
        : "r"(a0), "r"(a1), "r"(a2), "r"(a3), "r"(b0), "r"(b1));
}

__device__ __forceinline__ uint32_t pack_bf16(float lo, float hi) {
    __nv_bfloat162 v = __floats2bfloat162_rn(lo, hi);
    return *(uint32_t*)&v;
}

// ===========================================================================
// k_attn_mma smem layout (u32 units). 1 window (64 tokens) per block.
//   sbias [0, 900)            clipped rel-bias LUT (4 heads x 225), fp32
//   Ws    [904, +96*52)       staged weight chunk [n][k] bf16 pairs
//   A32   [.., +64*52)        LN1'd tokens bf16 [row][kpair]; later O (attn out)
//   Q32   [.., +64*68)        Q bf16 [token][head*16 + dpair], pads 12..15 = 0
//   K32   [.., +64*68)        K bf16, same layout
//   VT    [.., +96*36)        V^T bf16 [h*24+d][token pair]
// ===========================================================================
#define AQ_SB   0
#define AQ_W    904
#define AQ_A    (AQ_W + 96*52)    // 5896
#define AQ_Q    (AQ_A + 64*52)    // 9224
#define AQ_K    (AQ_Q + 64*68)    // 13576
#define AQ_V    (AQ_K + 64*68)    // 17928
#define SMEM_A_U32 (AQ_V + 96*36) // 21384
#define SMEM_A (SMEM_A_U32*4)     // 85536 bytes

// ===========================================================================
// k_mlp_mma smem layout (u32 units) — unchanged from round 9
// ===========================================================================
#define SB1_O  0
#define SB2_O  384
#define A_O    512
#define H_O    (A_O + 128*52)
#define W1_O   (H_O + 128*36)
#define W2_O   (W1_O + 64*52)
#define SMEM_M_U32 (W2_O + 96*36)
#define SMEM_M (SMEM_M_U32*4)

// ---------------------------------------------------------------------------
// Kernel 1 (HMMA): per-window LN1 + shift + QKV + attention + proj + residual
// ---------------------------------------------------------------------------
__global__ __launch_bounds__(128, 2) void k_attn_mma(
    const float* __restrict__ x,
    const float* __restrict__ n1g, const float* __restrict__ n1b,
    const float* __restrict__ qkvw, const float* __restrict__ qkvb,
    const float* __restrict__ relb,
    const float* __restrict__ pw,  const float* __restrict__ pb)
{
    extern __shared__ uint32_t smu[];
    float*    sbias = (float*)(smu + AQ_SB);
    uint32_t* Ws  = smu + AQ_W;
    uint32_t* A32 = smu + AQ_A;   // aliased as O after QKV phase
    uint32_t* Q32 = smu + AQ_Q;
    uint32_t* K32 = smu + AQ_K;
    uint32_t* VT  = smu + AQ_V;

    const int t    = threadIdx.x;
    const int wid  = t >> 5;
    const int lane = t & 31;
    const int g    = lane >> 2;
    const int tig  = lane & 3;
    const int r0   = wid * 16;

    const int win = blockIdx.x;
    const int b   = win >> 10;
    const int wr  = win & 1023;
    const int wh  = wr >> 5;
    const int ww  = wr & 31;
    const bool edgeH = (wh == 31), edgeW = (ww == 31);
    const float SCALE = rsqrtf((float)HD);

    // clipped rel-bias LUT
    for (int e = t; e < 900; e += 128) {
        const int h = e / 225, idx = e - h*225;
        float bv = relb[idx*NHEAD + h];
        sbias[e] = fminf(fmaxf(bv, -5.f), 5.f);
    }
    // zero per-head k-pad pairs (12..15) in Q32/K32
    for (int i = t; i < 64*16; i += 128) {
        const int row = i >> 4, q = i & 15;
        const int idx = row*68 + (q >> 2)*16 + 12 + (q & 3);
        Q32[idx] = 0; K32[idx] = 0;
    }

    // ---- LN1 with cyclic-shift gather -> A32 bf16 (2 threads/row) ----
    {
        const int row = t >> 1, q = t & 1;
        const int i = row >> 3, j = row & 7;
        const int h0 = (wh*8 + i + SHIFT) & 255;
        const int w0 = (ww*8 + j + SHIFT) & 255;
        const float* xr = x + (((size_t)b*HH + h0)*WW2 + w0)*CDIM + q*48;
        float v[48];
        float s1 = 0.f, s2 = 0.f;
#pragma unroll
        for (int k = 0; k < 12; k++) {
            float4 f = ((const float4*)xr)[k];
            v[4*k+0]=f.x; v[4*k+1]=f.y; v[4*k+2]=f.z; v[4*k+3]=f.w;
            s1 += f.x+f.y+f.z+f.w;
            s2 += f.x*f.x+f.y*f.y+f.z*f.z+f.w*f.w;
        }
        s1 += __shfl_xor_sync(0xffffffffu, s1, 1);
        s2 += __shfl_xor_sync(0xffffffffu, s2, 1);
        const float mean = s1 * (1.f/96.f);
        const float var  = s2 * (1.f/96.f) - mean*mean;
        const float rstd = rsqrtf(var + 1e-5f);
#pragma unroll
        for (int k = 0; k < 24; k++) {
            const int c = q*48 + 2*k;
            float a0 = (v[2*k]   - mean)*rstd*n1g[c]   + n1b[c];
            float a1 = (v[2*k+1] - mean)*rstd*n1g[c+1] + n1b[c+1];
            A32[row*52 + q*24 + k] = pack_bf16(a0, a1);
        }
    }

    // ---- QKV: 3 chunk GEMMs (Q, K, V), each [64x96] @ [96x96]^T ----
    for (int ch = 0; ch < 3; ch++) {
        const int c0 = ch * 96;
        __syncthreads();   // previous Ws consumed / A32 ready
#pragma unroll
        for (int i = 0; i < 36; i++) {
            const int p = t + 128*i;            // p < 4608
            const int kp = p / 96, n = p % 96;  // kp < 48
            Ws[n*52 + kp] = pack_bf16(qkvw[(size_t)(2*kp)*288 + c0 + n],
                                      qkvw[(size_t)(2*kp+1)*288 + c0 + n]);
        }
        __syncthreads();

        float d1[12][4];
#pragma unroll
        for (int nt = 0; nt < 12; nt++)
#pragma unroll
            for (int i = 0; i < 4; i++) d1[nt][i] = 0.f;
#pragma unroll
        for (int s = 0; s < 6; s++) {
            const int kp0 = 8*s;
            uint32_t a0 = A32[(r0+g)*52   + kp0 + tig];
            uint32_t a1 = A32[(r0+g+8)*52 + kp0 + tig];
            uint32_t a2 = A32[(r0+g)*52   + kp0 + 4 + tig];
            uint32_t a3 = A32[(r0+g+8)*52 + kp0 + 4 + tig];
#pragma unroll
            for (int nt = 0; nt < 12; nt++) {
                const int n = nt*8 + g;
                mma_bf16(d1[nt], a0, a1, a2, a3,
                         Ws[n*52 + kp0 + tig], Ws[n*52 + kp0 + 4 + tig]);
            }
        }

        if (ch < 2) {
            uint32_t* DST = (ch == 0) ? Q32 : K32;
            const float scl = (ch == 0) ? SCALE : 1.f;
#pragma unroll
            for (int nt = 0; nt < 12; nt++) {
                const int c = 8*nt + 2*tig;
                const int h = c / 24, dd = c - 24*h;
                const float bb0 = __ldg(qkvb + c0 + c), bb1 = __ldg(qkvb + c0 + c + 1);
                DST[(r0+g)*68   + h*16 + (dd>>1)] =
                    pack_bf16((d1[nt][0]+bb0)*scl, (d1[nt][1]+bb1)*scl);
                DST[(r0+g+8)*68 + h*16 + (dd>>1)] =
                    pack_bf16((d1[nt][2]+bb0)*scl, (d1[nt][3]+bb1)*scl);
            }
        } else {
            // V transposed: VT[c][token] (c = h*24+d = global dim index)
#pragma unroll
            for (int nt = 0; nt < 12; nt++) {
                const int c = 8*nt + 2*tig;
                const float bb0 = __ldg(qkvb + c0 + c), bb1 = __ldg(qkvb + c0 + c + 1);
                __nv_bfloat16* v0p = (__nv_bfloat16*)(VT + (size_t)c*36);
                __nv_bfloat16* v1p = (__nv_bfloat16*)(VT + (size_t)(c+1)*36);
                v0p[r0+g]   = __float2bfloat16(d1[nt][0] + bb0);
                v1p[r0+g]   = __float2bfloat16(d1[nt][1] + bb1);
                v0p[r0+g+8] = __float2bfloat16(d1[nt][2] + bb0);
                v1p[r0+g+8] = __float2bfloat16(d1[nt][3] + bb1);
            }
        }
    }
    __syncthreads();   // Q/K/VT complete; A32 now dead -> reuse as O

    // ---- attention: warp = head ----
    {
        const int h  = wid;
        const int hq = h*16;
#pragma unroll
        for (int m = 0; m < 4; m++) {
            const int rA = m*16;
            float d[8][4];
#pragma unroll
            for (int nt = 0; nt < 8; nt++)
#pragma unroll
                for (int i = 0; i < 4; i++) d[nt][i] = 0.f;

            // scores = Q @ K^T  (2 k-steps; pads are zero)
#pragma unroll
            for (int s = 0; s < 2; s++) {
                const int kp0 = 8*s;
                uint32_t a0 = Q32[(rA+g)*68   + hq + kp0 + tig];
                uint32_t a1 = Q32[(rA+g+8)*68 + hq + kp0 + tig];
                uint32_t a2 = Q32[(rA+g)*68   + hq + kp0 + 4 + tig];
                uint32_t a3 = Q32[(rA+g+8)*68 + hq + kp0 + 4 + tig];
#pragma unroll
                for (int nt = 0; nt < 8; nt++) {
                    const int n = nt*8 + g;
                    mma_bf16(d[nt], a0, a1, a2, a3,
                             K32[n*68 + hq + kp0 + tig], K32[n*68 + hq + kp0 + 4 + tig]);
                }
            }

            // mask + bias + clip
            const int n1a = rA + g, n1b2 = rA + g + 8;
            const int i1a = n1a >> 3, j1a = n1a & 7;
            const int i1b = n1b2 >> 3, j1b = n1b2 & 7;
            const int r1a = (edgeH ? ((i1a < 4) ? 1 : 2) : 0)*3 + (edgeW ? ((j1a < 4) ? 1 : 2) : 0);
            const int r1b = (edgeH ? ((i1b < 4) ? 1 : 2) : 0)*3 + (edgeW ? ((j1b < 4) ? 1 : 2) : 0);
#pragma unroll
            for (int nt = 0; nt < 8; nt++) {
#pragma unroll
                for (int e = 0; e < 2; e++) {
                    const int cc = nt*8 + 2*tig + e;
                    const int i2 = cc >> 3, j2 = cc & 7;
                    const int r2 = (edgeH ? ((i2 < 4) ? 1 : 2) : 0)*3 + (edgeW ? ((j2 < 4) ? 1 : 2) : 0);
                    const float ba = sbias[h*225 + (i1a-i2+7)*15 + (j1a-j2+7)];
                    const float bbv = sbias[h*225 + (i1b-i2+7)*15 + (j1b-j2+7)];
                    float va = d[nt][e]   + ((r1a == r2) ? 0.f : -1e9f) + ba;
                    float vb = d[nt][e+2] + ((r1b == r2) ? 0.f : -1e9f) + bbv;
                    d[nt][e]   = fminf(fmaxf(va, -10.f), 10.f);
                    d[nt][e+2] = fminf(fmaxf(vb, -10.f), 10.f);
                }
            }

            // softmax (rows g and g+8, reduced over tig quad)
            float mx0 = -1e30f, mx1 = -1e30f;
#pragma unroll
            for (int nt = 0; nt < 8; nt++) {
                mx0 = fmaxf(mx0, fmaxf(d[nt][0], d[nt][1]));
                mx1 = fmaxf(mx1, fmaxf(d[nt][2], d[nt][3]));
            }
            mx0 = fmaxf(mx0, __shfl_xor_sync(0xffffffffu, mx0, 1));
            mx1 = fmaxf(mx1, __shfl_xor_sync(0xffffffffu, mx1, 1));
            mx0 = fmaxf(mx0, __shfl_xor_sync(0xffffffffu, mx0, 2));
            mx1 = fmaxf(mx1, __shfl_xor_sync(0xffffffffu, mx1, 2));
            float sm0 = 0.f, sm1 = 0.f;
#pragma unroll
            for (int nt = 0; nt < 8; nt++) {
                d[nt][0] = __expf(d[nt][0] - mx0); sm0 += d[nt][0];
                d[nt][1] = __expf(d[nt][1] - mx0); sm0 += d[nt][1];
                d[nt][2] = __expf(d[nt][2] - mx1); sm1 += d[nt][2];
                d[nt][3] = __expf(d[nt][3] - mx1); sm1 += d[nt][3];
            }
            sm0 += __shfl_xor_sync(0xffffffffu, sm0, 1);
            sm1 += __shfl_xor_sync(0xffffffffu, sm1, 1);
            sm0 += __shfl_xor_sync(0xffffffffu, sm0, 2);
            sm1 += __shfl_xor_sync(0xffffffffu, sm1, 2);
            const float inv0 = 1.f / sm0, inv1 = 1.f / sm1;
#pragma unroll
            for (int nt = 0; nt < 8; nt++) {
                d[nt][0] *= inv0; d[nt][1] *= inv0;
                d[nt][2] *= inv1; d[nt][3] *= inv1;
            }

            // AV: P (regs -> A frags) @ VT
            float oacc[3][4];
#pragma unroll
            for (int vt = 0; vt < 3; vt++)
#pragma unroll
                for (int i = 0; i < 4; i++) oacc[vt][i] = 0.f;
#pragma unroll
            for (int s = 0; s < 4; s++) {
                uint32_t a0 = pack_bf16(d[2*s][0],   d[2*s][1]);
                uint32_t a1 = pack_bf16(d[2*s][2],   d[2*s][3]);
                uint32_t a2 = pack_bf16(d[2*s+1][0], d[2*s+1][1]);
                uint32_t a3 = pack_bf16(d[2*s+1][2], d[2*s+1][3]);
                const int kp0 = 8*s;
#pragma unroll
                for (int vt = 0; vt < 3; vt++) {
                    const int n = vt*8 + g;   // head dim 0..23
                    mma_bf16(oacc[vt], a0, a1, a2, a3,
                             VT[(h*24+n)*36 + kp0 + tig], VT[(h*24+n)*36 + kp0 + 4 + tig]);
                }
            }
            // write O (aliases A32): col = h*24 + vt*8 + 2tig
#pragma unroll
            for (int vt = 0; vt < 3; vt++) {
                const int pi = h*12 + vt*4 + tig;
                A32[(rA+g)*52   + pi] = pack_bf16(oacc[vt][0], oacc[vt][1]);
                A32[(rA+g+8)*52 + pi] = pack_bf16(oacc[vt][2], oacc[vt][3]);
            }
        }
    }
    __syncthreads();   // O complete, Ws (V chunk) consumed

    // ---- proj: O[64x96] @ pw^T + un-shift residual -> g_x1 ----
#pragma unroll
    for (int i = 0; i < 36; i++) {
        const int p = t + 128*i;
        const int kp = p / 96, n = p % 96;
        Ws[n*52 + kp] = pack_bf16(pw[(size_t)(2*kp)*96 + n],
                                  pw[(size_t)(2*kp+1)*96 + n]);
    }
    __syncthreads();
    {
        float d2[12][4];
#pragma unroll
        for (int nt = 0; nt < 12; nt++)
#pragma unroll
            for (int i = 0; i < 4; i++) d2[nt][i] = 0.f;
#pragma unroll
        for (int s = 0; s < 6; s++) {
            const int kp0 = 8*s;
            uint32_t a0 = A32[(r0+g)*52   + kp0 + tig];
            uint32_t a1 = A32[(r0+g+8)*52 + kp0 + tig];
            uint32_t a2 = A32[(r0+g)*52   + kp0 + 4 + tig];
            uint32_t a3 = A32[(r0+g+8)*52 + kp0 + 4 + tig];
#pragma unroll
            for (int nt = 0; nt < 12; nt++) {
                const int n = nt*8 + g;
                mma_bf16(d2[nt], a0, a1, a2, a3,
                         Ws[n*52 + kp0 + tig], Ws[n*52 + kp0 + 4 + tig]);
            }
        }
        // epilogue: un-shift + residual
        const int ra = r0 + g, rb2 = r0 + g + 8;
        const int ia = ra >> 3, ja = ra & 7;
        const int ib = rb2 >> 3, jb = rb2 & 7;
        const size_t basea = (((size_t)b*HH + ((wh*8 + ia + SHIFT) & 255))*WW2
                              + ((ww*8 + ja + SHIFT) & 255))*CDIM;
        const size_t baseb = (((size_t)b*HH + ((wh*8 + ib + SHIFT) & 255))*WW2
                              + ((ww*8 + jb + SHIFT) & 255))*CDIM;
#pragma unroll
        for (int nt = 0; nt < 12; nt++) {
            const int c = 8*nt + 2*tig;
            const float p0v = __ldg(pb + c), p1v = __ldg(pb + c + 1);
            float2 xa = *(const float2*)(x + basea + c);
            float2 xb = *(const float2*)(x + baseb + c);
            float2 oa, ob;
            oa.x = xa.x + d2[nt][0] + p0v;
            oa.y = xa.y + d2[nt][1] + p1v;
            ob.x = xb.x + d2[nt][2] + p0v;
            ob.y = xb.y + d2[nt][3] + p1v;
            *(float2*)(g_x1 + basea + c) = oa;
            *(float2*)(g_x1 + baseb + c) = ob;
        }
    }
}

// ---------------------------------------------------------------------------
// Kernel 2 (HMMA): 128 pixels/block  LN2 + MLP + residual  (unchanged R9)
// ---------------------------------------------------------------------------
__global__ __launch_bounds__(256, 2) void k_mlp_mma(
    const float* __restrict__ n2g, const float* __restrict__ n2b,
    const float* __restrict__ w1,  const float* __restrict__ b1,
    const float* __restrict__ w2,  const float* __restrict__ b2,
    float* __restrict__ out)
{
    extern __shared__ uint32_t smu[];
    float*    sb1 = (float*)(smu + SB1_O);
    float*    sb2 = (float*)(smu + SB2_O);
    uint32_t* A32 = smu + A_O;
    uint32_t* H32 = smu + H_O;
    uint32_t* W1s = smu + W1_O;
    uint32_t* W2s = smu + W2_O;

    const int t    = threadIdx.x;
    const int wid  = t >> 5;
    const int lane = t & 31;
    const int g    = lane >> 2;
    const int tig  = lane & 3;
    const int r0   = wid * 16;
    const size_t p0 = (size_t)blockIdx.x * 128;

    for (int i = t; i < 384; i += 256) sb1[i] = b1[i];
    if (t < 96) sb2[t] = b2[t];

    {
        const int row = t >> 1, q = t & 1;
        const float* xr = g_x1 + (p0 + row)*96 + q*48;
        float v[48];
        float s1 = 0.f, s2 = 0.f;
#pragma unroll
        for (int k = 0; k < 12; k++) {
            float4 f = ((const float4*)xr)[k];
            v[4*k+0]=f.x; v[4*k+1]=f.y; v[4*k+2]=f.z; v[4*k+3]=f.w;
            s1 += f.x+f.y+f.z+f.w;
            s2 += f.x*f.x+f.y*f.y+f.z*f.z+f.w*f.w;
        }
        s1 += __shfl_xor_sync(0xffffffffu, s1, 1);
        s2 += __shfl_xor_sync(0xffffffffu, s2, 1);
        const float mean = s1 * (1.f/96.f);
        const float var  = s2 * (1.f/96.f) - mean*mean;
        const float rstd = rsqrtf(var + 1e-5f);
#pragma unroll
        for (int k = 0; k < 24; k++) {
            const int c = q*48 + 2*k;
            float a0 = (v[2*k]   - mean)*rstd*n2g[c]   + n2b[c];
            float a1 = (v[2*k+1] - mean)*rstd*n2g[c+1] + n2b[c+1];
            A32[row*52 + q*24 + k] = pack_bf16(a0, a1);
        }
    }

    float d2[12][4];
#pragma unroll
    for (int nt = 0; nt < 12; nt++)
#pragma unroll
        for (int i = 0; i < 4; i++) d2[nt][i] = 0.f;

    for (int c = 0; c < 6; c++) {
        const int co0 = c*64;
        __syncthreads();

#pragma unroll
        for (int i = 0; i < 12; i++) {
            const int p = t + 256*i;
            const int n = p & 63, kp = p >> 6;
            W1s[n*52 + kp] = pack_bf16(w1[(size_t)(2*kp)*384   + co0 + n],
                                       w1[(size_t)(2*kp+1)*384 + co0 + n]);
        }
#pragma unroll
        for (int i = 0; i < 12; i++) {
            const int p = t + 256*i;
            const int n = p % 96, kp = p / 96;
            W2s[n*36 + kp] = pack_bf16(w2[(size_t)(co0+2*kp)*96   + n],
                                       w2[(size_t)(co0+2*kp+1)*96 + n]);
        }
        __syncthreads();

        float d1[8][4];
#pragma unroll
        for (int nt = 0; nt < 8; nt++)
#pragma unroll
            for (int i = 0; i < 4; i++) d1[nt][i] = 0.f;

#pragma unroll
        for (int s = 0; s < 6; s++) {
            const int kp0 = 8*s;
            uint32_t a0 = A32[(r0+g)*52   + kp0 + tig];
            uint32_t a1 = A32[(r0+g+8)*52 + kp0 + tig];
            uint32_t a2 = A32[(r0+g)*52   + kp0 + 4 + tig];
            uint32_t a3 = A32[(r0+g+8)*52 + kp0 + 4 + tig];
#pragma unroll
            for (int nt = 0; nt < 8; nt++) {
                const int n = nt*8 + g;
                mma_bf16(d1[nt], a0, a1, a2, a3,
                         W1s[n*52 + kp0 + tig], W1s[n*52 + kp0 + 4 + tig]);
            }
        }

#pragma unroll
        for (int nt = 0; nt < 8; nt++) {
            const int cn = nt*8 + 2*tig;
            const float bb0 = sb1[co0 + cn], bb1 = sb1[co0 + cn + 1];
            float v0 = d1[nt][0] + bb0, v1 = d1[nt][1] + bb1;
            float v2 = d1[nt][2] + bb0, v3 = d1[nt][3] + bb1;
            v0 = 0.5f*v0*(1.f + erff(v0*0.7071067811865476f));
            v1 = 0.5f*v1*(1.f + erff(v1*0.7071067811865476f));
            v2 = 0.5f*v2*(1.f + erff(v2*0.7071067811865476f));
            v3 = 0.5f*v3*(1.f + erff(v3*0.7071067811865476f));
            H32[(r0+g)*36   + nt*4 + tig] = pack_bf16(v0, v1);
            H32[(r0+g+8)*36 + nt*4 + tig] = pack_bf16(v2, v3);
        }
        __syncwarp();

#pragma unroll
        for (int s = 0; s < 4; s++) {
            const int kp0 = 8*s;
            uint32_t a0 = H32[(r0+g)*36   + kp0 + tig];
            uint32_t a1 = H32[(r0+g+8)*36 + kp0 + tig];
            uint32_t a2 = H32[(r0+g)*36   + kp0 + 4 + tig];
            uint32_t a3 = H32[(r0+g+8)*36 + kp0 + 4 + tig];
#pragma unroll
            for (int nt = 0; nt < 12; nt++) {
                const int n = nt*8 + g;
                mma_bf16(d2[nt], a0, a1, a2, a3,
                         W2s[n*36 + kp0 + tig], W2s[n*36 + kp0 + 4 + tig]);
            }
        }
    }

#pragma unroll
    for (int nt = 0; nt < 12; nt++) {
        const int col = nt*8 + 2*tig;
        const float bb0 = sb2[col], bb1 = sb2[col + 1];
        const size_t i0 = (p0 + r0 + g)*96 + col;
        const size_t i1 = (p0 + r0 + g + 8)*96 + col;
        float2 x0 = *(const float2*)(g_x1 + i0);
        float2 x1v = *(const float2*)(g_x1 + i1);
        float2 o0, o1;
        o0.x = x0.x + d2[nt][0] + bb0;
        o0.y = x0.y + d2[nt][1] + bb1;
        o1.x = x1v.x + d2[nt][2] + bb0;
        o1.y = x1v.y + d2[nt][3] + bb1;
        *(float2*)(out + i0) = o0;
        *(float2*)(out + i1) = o1;
    }
}

// ---------------------------------------------------------------------------
extern "C" void kernel_launch(void* const* d_in, const int* in_sizes, int n_in,
                              void* d_out, int out_size)
{
    const float* x    = (const float*)d_in[0];
    const float* n1g  = (const float*)d_in[1];
    const float* n1b  = (const float*)d_in[2];
    const float* qkvw = (const float*)d_in[3];
    const float* qkvb = (const float*)d_in[4];
    const float* relb = (const float*)d_in[5];
    const float* pw   = (const float*)d_in[6];
    const float* pb   = (const float*)d_in[7];
    const float* n2g  = (const float*)d_in[8];
    const float* n2b  = (const float*)d_in[9];
    const float* w1   = (const float*)d_in[10];
    const float* b1   = (const float*)d_in[11];
    const float* w2   = (const float*)d_in[12];
    const float* b2   = (const float*)d_in[13];
    float* out = (float*)d_out;

    cudaFuncSetAttribute(k_attn_mma, cudaFuncAttributeMaxDynamicSharedMemorySize, SMEM_A);
    cudaFuncSetAttribute(k_mlp_mma,  cudaFuncAttributeMaxDynamicSharedMemorySize, SMEM_M);

    k_attn_mma<<<NWIN, 128, SMEM_A>>>(x, n1g, n1b, qkvw, qkvb, relb, pw, pb);
    k_mlp_mma<<<NPIX/128, 256, SMEM_M>>>(n2g, n2b, w1, b1, w2, b2, out);
}

// round 11
// speedup vs baseline: 4.5154x; 1.0258x over previous
#include <cuda_runtime.h>
#include <cuda_bf16.h>
#include <math.h>
#include <stdint.h>

// Problem constants
#define BB 8
#define HH 256
#define WW2 256
#define CDIM 96
#define NHEAD 4
#define HD 24
#define WS 8
#define NTOK 64
#define SHIFT 4
#define NWIN 8192     // B * 32 * 32
#define NPIX (BB*HH*WW2)

// scratch: x1 = shortcut + attention branch
static __device__ float g_x1[(size_t)BB*HH*WW2*CDIM];

// bf16 mma m16n8k16 (portable PTX, runs on HMMA)
__device__ __forceinline__ void mma_bf16(float* d, uint32_t a0, uint32_t a1,
                                         uint32_t a2, uint32_t a3,
                                         uint32_t b0, uint32_t b1) {
    asm volatile(
        "mma.sync.aligned.m16n8k16.row.col.f32.bf16.bf16.f32 "
        "{%0,%1,%2,%3}, {%4,%5,%6,%7}, {%8,%9}, {%0,%1,%2,%3};"
        : "+f"(d[0]), "+f"(d[1]), "+f"(d[2]), "+f"(d[3])
        : "r"(a0), "r"(a1), "r"(a2), "r"(a3), "r"(b0), "r"(b1));
}

__device__ __forceinline__ void ldsm_x4(uint32_t& r0, uint32_t& r1,
                                        uint32_t& r2, uint32_t& r3, uint32_t saddr) {
    asm volatile("ldmatrix.sync.aligned.m8n8.x4.shared.b16 {%0,%1,%2,%3}, [%4];"
                 : "=r"(r0), "=r"(r1), "=r"(r2), "=r"(r3) : "r"(saddr));
}
__device__ __forceinline__ void ldsm_x2(uint32_t& r0, uint32_t& r1, uint32_t saddr) {
    asm volatile("ldmatrix.sync.aligned.m8n8.x2.shared.b16 {%0,%1}, [%2];"
                 : "=r"(r0), "=r"(r1) : "r"(saddr));
}

__device__ __forceinline__ uint32_t pack_bf16(float lo, float hi) {
    __nv_bfloat162 v = __floats2bfloat162_rn(lo, hi);
    return *(uint32_t*)&v;
}

// ===========================================================================
// k_attn_mma smem layout (u32 units). 1 window (64 tokens) per block.
// ===========================================================================
#define AQ_SB   0
#define AQ_W    904
#define AQ_A    (AQ_W + 96*52)    // 5896
#define AQ_Q    (AQ_A + 64*52)    // 9224
#define AQ_K    (AQ_Q + 64*68)    // 13576
#define AQ_V    (AQ_K + 64*68)    // 17928
#define SMEM_A_U32 (AQ_V + 96*36) // 21384
#define SMEM_A (SMEM_A_U32*4)     // 85536 bytes

// ===========================================================================
// k_mlp_mma smem layout (u32 units)
// ===========================================================================
#define SB1_O  0
#define SB2_O  384
#define A_O    512
#define H_O    (A_O + 128*52)
#define W1_O   (H_O + 128*36)
#define W2_O   (W1_O + 64*52)
#define SMEM_M_U32 (W2_O + 96*36)
#define SMEM_M (SMEM_M_U32*4)

// ---------------------------------------------------------------------------
// Kernel 1 (HMMA): per-window LN1 + shift + QKV + attention + proj + residual
// ---------------------------------------------------------------------------
__global__ __launch_bounds__(128, 2) void k_attn_mma(
    const float* __restrict__ x,
    const float* __restrict__ n1g, const float* __restrict__ n1b,
    const float* __restrict__ qkvw, const float* __restrict__ qkvb,
    const float* __restrict__ relb,
    const float* __restrict__ pw,  const float* __restrict__ pb)
{
    extern __shared__ uint32_t smu[];
    float*    sbias = (float*)(smu + AQ_SB);
    uint32_t* Ws  = smu + AQ_W;
    uint32_t* A32 = smu + AQ_A;   // aliased as O after QKV phase
    uint32_t* Q32 = smu + AQ_Q;
    uint32_t* K32 = smu + AQ_K;
    uint32_t* VT  = smu + AQ_V;

    const int t    = threadIdx.x;
    const int wid  = t >> 5;
    const int lane = t & 31;
    const int g    = lane >> 2;
    const int tig  = lane & 3;
    const int r0   = wid * 16;

    // ldmatrix per-lane address components
    const uint32_t lrow  = lane & 15;                 // A rows
    const uint32_t lhi16 = ((lane >> 4) & 1) * 16;    // A k+8 half
    const uint32_t brow  = lane & 7;                  // B rows
    const uint32_t bhi16 = ((lane >> 3) & 1) * 16;    // B k+8 half

    const uint32_t As = (uint32_t)__cvta_generic_to_shared(A32);
    const uint32_t Qs = (uint32_t)__cvta_generic_to_shared(Q32);
    const uint32_t Ks = (uint32_t)__cvta_generic_to_shared(K32);
    const uint32_t Vs = (uint32_t)__cvta_generic_to_shared(VT);
    const uint32_t Wb = (uint32_t)__cvta_generic_to_shared(Ws);

    const int win = blockIdx.x;
    const int b   = win >> 10;
    const int wr  = win & 1023;
    const int wh  = wr >> 5;
    const int ww  = wr & 31;
    const bool edgeH = (wh == 31), edgeW = (ww == 31);
    const float SCALE = rsqrtf((float)HD);

    // clipped rel-bias LUT
    for (int e = t; e < 900; e += 128) {
        const int h = e / 225, idx = e - h*225;
        float bv = relb[idx*NHEAD + h];
        sbias[e] = fminf(fmaxf(bv, -5.f), 5.f);
    }
    // zero per-head k-pad pairs (12..15) in Q32/K32
    for (int i = t; i < 64*16; i += 128) {
        const int row = i >> 4, q = i & 15;
        const int idx = row*68 + (q >> 2)*16 + 12 + (q & 3);
        Q32[idx] = 0; K32[idx] = 0;
    }

    // ---- LN1 with cyclic-shift gather -> A32 bf16 (2 threads/row) ----
    {
        const int row = t >> 1, q = t & 1;
        const int i = row >> 3, j = row & 7;
        const int h0 = (wh*8 + i + SHIFT) & 255;
        const int w0 = (ww*8 + j + SHIFT) & 255;
        const float* xr = x + (((size_t)b*HH + h0)*WW2 + w0)*CDIM + q*48;
        float v[48];
        float s1 = 0.f, s2 = 0.f;
#pragma unroll
        for (int k = 0; k < 12; k++) {
            float4 f = ((const float4*)xr)[k];
            v[4*k+0]=f.x; v[4*k+1]=f.y; v[4*k+2]=f.z; v[4*k+3]=f.w;
            s1 += f.x+f.y+f.z+f.w;
            s2 += f.x*f.x+f.y*f.y+f.z*f.z+f.w*f.w;
        }
        s1 += __shfl_xor_sync(0xffffffffu, s1, 1);
        s2 += __shfl_xor_sync(0xffffffffu, s2, 1);
        const float mean = s1 * (1.f/96.f);
        const float var  = s2 * (1.f/96.f) - mean*mean;
        const float rstd = rsqrtf(var + 1e-5f);
#pragma unroll
        for (int k = 0; k < 24; k++) {
            const int c = q*48 + 2*k;
            float a0 = (v[2*k]   - mean)*rstd*n1g[c]   + n1b[c];
            float a1 = (v[2*k+1] - mean)*rstd*n1g[c+1] + n1b[c+1];
            A32[row*52 + q*24 + k] = pack_bf16(a0, a1);
        }
    }

    // ---- QKV: 3 chunk GEMMs (Q, K, V), each [64x96] @ [96x96]^T ----
    for (int ch = 0; ch < 3; ch++) {
        const int c0 = ch * 96;
        __syncthreads();   // previous Ws consumed / A32 ready
#pragma unroll
        for (int i = 0; i < 36; i++) {
            const int p = t + 128*i;            // p < 4608
            const int kp = p / 96, n = p % 96;  // kp < 48
            Ws[n*52 + kp] = pack_bf16(qkvw[(size_t)(2*kp)*288 + c0 + n],
                                      qkvw[(size_t)(2*kp+1)*288 + c0 + n]);
        }
        __syncthreads();

        float d1[12][4];
#pragma unroll
        for (int nt = 0; nt < 12; nt++)
#pragma unroll
            for (int i = 0; i < 4; i++) d1[nt][i] = 0.f;
#pragma unroll
        for (int s = 0; s < 6; s++) {
            uint32_t a0, a1, a2, a3;
            ldsm_x4(a0, a1, a2, a3, As + ((r0+lrow)*52)*4 + lhi16 + s*32);
            const uint32_t bb = Wb + (brow*52)*4 + bhi16 + s*32;
#pragma unroll
            for (int nt = 0; nt < 12; nt++) {
                uint32_t b0, b1;
                ldsm_x2(b0, b1, bb + nt*(8*52*4));
                mma_bf16(d1[nt], a0, a1, a2, a3, b0, b1);
            }
        }

        if (ch < 2) {
            uint32_t* DST = (ch == 0) ? Q32 : K32;
            const float scl = (ch == 0) ? SCALE : 1.f;
#pragma unroll
            for (int nt = 0; nt < 12; nt++) {
                const int c = 8*nt + 2*tig;
                const int h = c / 24, dd = c - 24*h;
                const float bb0 = __ldg(qkvb + c0 + c), bb1 = __ldg(qkvb + c0 + c + 1);
                DST[(r0+g)*68   + h*16 + (dd>>1)] =
                    pack_bf16((d1[nt][0]+bb0)*scl, (d1[nt][1]+bb1)*scl);
                DST[(r0+g+8)*68 + h*16 + (dd>>1)] =
                    pack_bf16((d1[nt][2]+bb0)*scl, (d1[nt][3]+bb1)*scl);
            }
        } else {
            // V transposed: VT[c][token]
#pragma unroll
            for (int nt = 0; nt < 12; nt++) {
                const int c = 8*nt + 2*tig;
                const float bb0 = __ldg(qkvb + c0 + c), bb1 = __ldg(qkvb + c0 + c + 1);
                __nv_bfloat16* v0p = (__nv_bfloat16*)(VT + (size_t)c*36);
                __nv_bfloat16* v1p = (__nv_bfloat16*)(VT + (size_t)(c+1)*36);
                v0p[r0+g]   = __float2bfloat16(d1[nt][0] + bb0);
                v1p[r0+g]   = __float2bfloat16(d1[nt][1] + bb1);
                v0p[r0+g+8] = __float2bfloat16(d1[nt][2] + bb0);
                v1p[r0+g+8] = __float2bfloat16(d1[nt][3] + bb1);
            }
        }
    }
    __syncthreads();   // Q/K/VT complete; A32 now dead -> reuse as O

    // ---- attention: warp = head ----
    {
        const int h  = wid;
#pragma unroll
        for (int m = 0; m < 4; m++) {
            const int rA = m*16;
            float d[8][4];
#pragma unroll
            for (int nt = 0; nt < 8; nt++)
#pragma unroll
                for (int i = 0; i < 4; i++) d[nt][i] = 0.f;

            // scores = Q @ K^T  (2 k-steps; pads are zero)
#pragma unroll
            for (int s = 0; s < 2; s++) {
                uint32_t a0, a1, a2, a3;
                ldsm_x4(a0, a1, a2, a3,
                        Qs + ((rA+lrow)*68)*4 + h*64 + lhi16 + s*32);
                const uint32_t bb = Ks + (brow*68)*4 + h*64 + bhi16 + s*32;
#pragma unroll
                for (int nt = 0; nt < 8; nt++) {
                    uint32_t b0, b1;
                    ldsm_x2(b0, b1, bb + nt*(8*68*4));
                    mma_bf16(d[nt], a0, a1, a2, a3, b0, b1);
                }
            }

            // mask + bias + clip
            const int n1a = rA + g, n1b2 = rA + g + 8;
            const int i1a = n1a >> 3, j1a = n1a & 7;
            const int i1b = n1b2 >> 3, j1b = n1b2 & 7;
            const int r1a = (edgeH ? ((i1a < 4) ? 1 : 2) : 0)*3 + (edgeW ? ((j1a < 4) ? 1 : 2) : 0);
            const int r1b = (edgeH ? ((i1b < 4) ? 1 : 2) : 0)*3 + (edgeW ? ((j1b < 4) ? 1 : 2) : 0);
#pragma unroll
            for (int nt = 0; nt < 8; nt++) {
#pragma unroll
                for (int e = 0; e < 2; e++) {
                    const int cc = nt*8 + 2*tig + e;
                    const int i2 = cc >> 3, j2 = cc & 7;
                    const int r2 = (edgeH ? ((i2 < 4) ? 1 : 2) : 0)*3 + (edgeW ? ((j2 < 4) ? 1 : 2) : 0);
                    const float ba = sbias[h*225 + (i1a-i2+7)*15 + (j1a-j2+7)];
                    const float bbv = sbias[h*225 + (i1b-i2+7)*15 + (j1b-j2+7)];
                    float va = d[nt][e]   + ((r1a == r2) ? 0.f : -1e9f) + ba;
                    float vb = d[nt][e+2] + ((r1b == r2) ? 0.f : -1e9f) + bbv;
                    d[nt][e]   = fminf(fmaxf(va, -10.f), 10.f);
                    d[nt][e+2] = fminf(fmaxf(vb, -10.f), 10.f);
                }
            }

            // softmax (rows g and g+8, reduced over tig quad)
            float mx0 = -1e30f, mx1 = -1e30f;
#pragma unroll
            for (int nt = 0; nt < 8; nt++) {
                mx0 = fmaxf(mx0, fmaxf(d[nt][0], d[nt][1]));
                mx1 = fmaxf(mx1, fmaxf(d[nt][2], d[nt][3]));
            }
            mx0 = fmaxf(mx0, __shfl_xor_sync(0xffffffffu, mx0, 1));
            mx1 = fmaxf(mx1, __shfl_xor_sync(0xffffffffu, mx1, 1));
            mx0 = fmaxf(mx0, __shfl_xor_sync(0xffffffffu, mx0, 2));
            mx1 = fmaxf(mx1, __shfl_xor_sync(0xffffffffu, mx1, 2));
            float sm0 = 0.f, sm1 = 0.f;
#pragma unroll
            for (int nt = 0; nt < 8; nt++) {
                d[nt][0] = __expf(d[nt][0] - mx0); sm0 += d[nt][0];
                d[nt][1] = __expf(d[nt][1] - mx0); sm0 += d[nt][1];
                d[nt][2] = __expf(d[nt][2] - mx1); sm1 += d[nt][2];
                d[nt][3] = __expf(d[nt][3] - mx1); sm1 += d[nt][3];
            }
            sm0 += __shfl_xor_sync(0xffffffffu, sm0, 1);
            sm1 += __shfl_xor_sync(0xffffffffu, sm1, 1);
            sm0 += __shfl_xor_sync(0xffffffffu, sm0, 2);
            sm1 += __shfl_xor_sync(0xffffffffu, sm1, 2);
            const float inv0 = 1.f / sm0, inv1 = 1.f / sm1;
#pragma unroll
            for (int nt = 0; nt < 8; nt++) {
                d[nt][0] *= inv0; d[nt][1] *= inv0;
                d[nt][2] *= inv1; d[nt][3] *= inv1;
            }

            // AV: P (regs -> A frags) @ VT
            float oacc[3][4];
#pragma unroll
            for (int vt = 0; vt < 3; vt++)
#pragma unroll
                for (int i = 0; i < 4; i++) oacc[vt][i] = 0.f;
#pragma unroll
            for (int s = 0; s < 4; s++) {
                uint32_t a0 = pack_bf16(d[2*s][0],   d[2*s][1]);
                uint32_t a1 = pack_bf16(d[2*s][2],   d[2*s][3]);
                uint32_t a2 = pack_bf16(d[2*s+1][0], d[2*s+1][1]);
                uint32_t a3 = pack_bf16(d[2*s+1][2], d[2*s+1][3]);
                const uint32_t bb = Vs + ((h*24 + brow)*36)*4 + bhi16 + s*32;
#pragma unroll
                for (int vt = 0; vt < 3; vt++) {
                    uint32_t b0, b1;
                    ldsm_x2(b0, b1, bb + vt*(8*36*4));
                    mma_bf16(oacc[vt], a0, a1, a2, a3, b0, b1);
                }
            }
            // write O (aliases A32): col = h*24 + vt*8 + 2tig
#pragma unroll
            for (int vt = 0; vt < 3; vt++) {
                const int pi = h*12 + vt*4 + tig;
                A32[(rA+g)*52   + pi] = pack_bf16(oacc[vt][0], oacc[vt][1]);
                A32[(rA+g+8)*52 + pi] = pack_bf16(oacc[vt][2], oacc[vt][3]);
            }
        }
    }
    __syncthreads();   // O complete, Ws (V chunk) consumed

    // ---- proj: O[64x96] @ pw^T + un-shift residual -> g_x1 ----
#pragma unroll
    for (int i = 0; i < 36; i++) {
        const int p = t + 128*i;
        const int kp = p / 96, n = p % 96;
        Ws[n*52 + kp] = pack_bf16(pw[(size_t)(2*kp)*96 + n],
                                  pw[(size_t)(2*kp+1)*96 + n]);
    }
    __syncthreads();
    {
        float d2[12][4];
#pragma unroll
        for (int nt = 0; nt < 12; nt++)
#pragma unroll
            for (int i = 0; i < 4; i++) d2[nt][i] = 0.f;
#pragma unroll
        for (int s = 0; s < 6; s++) {
            uint32_t a0, a1, a2, a3;
            ldsm_x4(a0, a1, a2, a3, As + ((r0+lrow)*52)*4 + lhi16 + s*32);
            const uint32_t bb = Wb + (brow*52)*4 + bhi16 + s*32;
#pragma unroll
            for (int nt = 0; nt < 12; nt++) {
                uint32_t b0, b1;
                ldsm_x2(b0, b1, bb + nt*(8*52*4));
                mma_bf16(d2[nt], a0, a1, a2, a3, b0, b1);
            }
        }
        // epilogue: un-shift + residual
        const int ra = r0 + g, rb2 = r0 + g + 8;
        const int ia = ra >> 3, ja = ra & 7;
        const int ib = rb2 >> 3, jb = rb2 & 7;
        const size_t basea = (((size_t)b*HH + ((wh*8 + ia + SHIFT) & 255))*WW2
                              + ((ww*8 + ja + SHIFT) & 255))*CDIM;
        const size_t baseb = (((size_t)b*HH + ((wh*8 + ib + SHIFT) & 255))*WW2
                              + ((ww*8 + jb + SHIFT) & 255))*CDIM;
#pragma unroll
        for (int nt = 0; nt < 12; nt++) {
            const int c = 8*nt + 2*tig;
            const float p0v = __ldg(pb + c), p1v = __ldg(pb + c + 1);
            float2 xa = *(const float2*)(x + basea + c);
            float2 xb = *(const float2*)(x + baseb + c);
            float2 oa, ob;
            oa.x = xa.x + d2[nt][0] + p0v;
            oa.y = xa.y + d2[nt][1] + p1v;
            ob.x = xb.x + d2[nt][2] + p0v;
            ob.y = xb.y + d2[nt][3] + p1v;
            *(float2*)(g_x1 + basea + c) = oa;
            *(float2*)(g_x1 + baseb + c) = ob;
        }
    }
}

// ---------------------------------------------------------------------------
// Kernel 2 (HMMA): 128 pixels/block  LN2 + MLP + residual
// ---------------------------------------------------------------------------
__global__ __launch_bounds__(256, 2) void k_mlp_mma(
    const float* __restrict__ n2g, const float* __restrict__ n2b,
    const float* __restrict__ w1,  const float* __restrict__ b1,
    const float* __restrict__ w2,  const float* __restrict__ b2,
    float* __restrict__ out)
{
    extern __shared__ uint32_t smu[];
    float*    sb1 = (float*)(smu + SB1_O);
    float*    sb2 = (float*)(smu + SB2_O);
    uint32_t* A32 = smu + A_O;
    uint32_t* H32 = smu + H_O;
    uint32_t* W1s = smu + W1_O;
    uint32_t* W2s = smu + W2_O;

    const int t    = threadIdx.x;
    const int wid  = t >> 5;
    const int lane = t & 31;
    const int g    = lane >> 2;
    const int tig  = lane & 3;
    const int r0   = wid * 16;
    const size_t p0 = (size_t)blockIdx.x * 128;

    const uint32_t lrow  = lane & 15;
    const uint32_t lhi16 = ((lane >> 4) & 1) * 16;
    const uint32_t brow  = lane & 7;
    const uint32_t bhi16 = ((lane >> 3) & 1) * 16;

    const uint32_t As  = (uint32_t)__cvta_generic_to_shared(A32);
    const uint32_t Hs  = (uint32_t)__cvta_generic_to_shared(H32);
    const uint32_t W1b = (uint32_t)__cvta_generic_to_shared(W1s);
    const uint32_t W2b = (uint32_t)__cvta_generic_to_shared(W2s);

    for (int i = t; i < 384; i += 256) sb1[i] = b1[i];
    if (t < 96) sb2[t] = b2[t];

    {
        const int row = t >> 1, q = t & 1;
        const float* xr = g_x1 + (p0 + row)*96 + q*48;
        float v[48];
        float s1 = 0.f, s2 = 0.f;
#pragma unroll
        for (int k = 0; k < 12; k++) {
            float4 f = ((const float4*)xr)[k];
            v[4*k+0]=f.x; v[4*k+1]=f.y; v[4*k+2]=f.z; v[4*k+3]=f.w;
            s1 += f.x+f.y+f.z+f.w;
            s2 += f.x*f.x+f.y*f.y+f.z*f.z+f.w*f.w;
        }
        s1 += __shfl_xor_sync(0xffffffffu, s1, 1);
        s2 += __shfl_xor_sync(0xffffffffu, s2, 1);
        const float mean = s1 * (1.f/96.f);
        const float var  = s2 * (1.f/96.f) - mean*mean;
        const float rstd = rsqrtf(var + 1e-5f);
#pragma unroll
        for (int k = 0; k < 24; k++) {
            const int c = q*48 + 2*k;
            float a0 = (v[2*k]   - mean)*rstd*n2g[c]   + n2b[c];
            float a1 = (v[2*k+1] - mean)*rstd*n2g[c+1] + n2b[c+1];
            A32[row*52 + q*24 + k] = pack_bf16(a0, a1);
        }
    }

    float d2[12][4];
#pragma unroll
    for (int nt = 0; nt < 12; nt++)
#pragma unroll
        for (int i = 0; i < 4; i++) d2[nt][i] = 0.f;

    for (int c = 0; c < 6; c++) {
        const int co0 = c*64;
        __syncthreads();

#pragma unroll
        for (int i = 0; i < 12; i++) {
            const int p = t + 256*i;
            const int n = p & 63, kp = p >> 6;
            W1s[n*52 + kp] = pack_bf16(w1[(size_t)(2*kp)*384   + co0 + n],
                                       w1[(size_t)(2*kp+1)*384 + co0 + n]);
        }
#pragma unroll
        for (int i = 0; i < 12; i++) {
            const int p = t + 256*i;
            const int n = p % 96, kp = p / 96;
            W2s[n*36 + kp] = pack_bf16(w2[(size_t)(co0+2*kp)*96   + n],
                                       w2[(size_t)(co0+2*kp+1)*96 + n]);
        }
        __syncthreads();

        float d1[8][4];
#pragma unroll
        for (int nt = 0; nt < 8; nt++)
#pragma unroll
            for (int i = 0; i < 4; i++) d1[nt][i] = 0.f;

#pragma unroll
        for (int s = 0; s < 6; s++) {
            uint32_t a0, a1, a2, a3;
            ldsm_x4(a0, a1, a2, a3, As + ((r0+lrow)*52)*4 + lhi16 + s*32);
            const uint32_t bb = W1b + (brow*52)*4 + bhi16 + s*32;
#pragma unroll
            for (int nt = 0; nt < 8; nt++) {
                uint32_t b0, b1;
                ldsm_x2(b0, b1, bb + nt*(8*52*4));
                mma_bf16(d1[nt], a0, a1, a2, a3, b0, b1);
            }
        }

#pragma unroll
        for (int nt = 0; nt < 8; nt++) {
            const int cn = nt*8 + 2*tig;
            const float bb0 = sb1[co0 + cn], bb1 = sb1[co0 + cn + 1];
            float v0 = d1[nt][0] + bb0, v1 = d1[nt][1] + bb1;
            float v2 = d1[nt][2] + bb0, v3 = d1[nt][3] + bb1;
            v0 = 0.5f*v0*(1.f + erff(v0*0.7071067811865476f));
            v1 = 0.5f*v1*(1.f + erff(v1*0.7071067811865476f));
            v2 = 0.5f*v2*(1.f + erff(v2*0.7071067811865476f));
            v3 = 0.5f*v3*(1.f + erff(v3*0.7071067811865476f));
            H32[(r0+g)*36   + nt*4 + tig] = pack_bf16(v0, v1);
            H32[(r0+g+8)*36 + nt*4 + tig] = pack_bf16(v2, v3);
        }
        __syncwarp();

#pragma unroll
        for (int s = 0; s < 4; s++) {
            uint32_t a0, a1, a2, a3;
            ldsm_x4(a0, a1, a2, a3, Hs + ((r0+lrow)*36)*4 + lhi16 + s*32);
            const uint32_t bb = W2b + (brow*36)*4 + bhi16 + s*32;
#pragma unroll
            for (int nt = 0; nt < 12; nt++) {
                uint32_t b0, b1;
                ldsm_x2(b0, b1, bb + nt*(8*36*4));
                mma_bf16(d2[nt], a0, a1, a2, a3, b0, b1);
            }
        }
    }

#pragma unroll
    for (int nt = 0; nt < 12; nt++) {
        const int col = nt*8 + 2*tig;
        const float bb0 = sb2[col], bb1 = sb2[col + 1];
        const size_t i0 = (p0 + r0 + g)*96 + col;
        const size_t i1 = (p0 + r0 + g + 8)*96 + col;
        float2 x0 = *(const float2*)(g_x1 + i0);
        float2 x1v = *(const float2*)(g_x1 + i1);
        float2 o0, o1;
        o0.x = x0.x + d2[nt][0] + bb0;
        o0.y = x0.y + d2[nt][1] + bb1;
        o1.x = x1v.x + d2[nt][2] + bb0;
        o1.y = x1v.y + d2[nt][3] + bb1;
        *(float2*)(out + i0) = o0;
        *(float2*)(out + i1) = o1;
    }
}

// ---------------------------------------------------------------------------
extern "C" void kernel_launch(void* const* d_in, const int* in_sizes, int n_in,
                              void* d_out, int out_size)
{
    const float* x    = (const float*)d_in[0];
    const float* n1g  = (const float*)d_in[1];
    const float* n1b  = (const float*)d_in[2];
    const float* qkvw = (const float*)d_in[3];
    const float* qkvb = (const float*)d_in[4];
    const float* relb = (const float*)d_in[5];
    const float* pw   = (const float*)d_in[6];
    const float* pb   = (const float*)d_in[7];
    const float* n2g  = (const float*)d_in[8];
    const float* n2b  = (const float*)d_in[9];
    const float* w1   = (const float*)d_in[10];
    const float* b1   = (const float*)d_in[11];
    const float* w2   = (const float*)d_in[12];
    const float* b2   = (const float*)d_in[13];
    float* out = (float*)d_out;

    cudaFuncSetAttribute(k_attn_mma, cudaFuncAttributeMaxDynamicSharedMemorySize, SMEM_A);
    cudaFuncSetAttribute(k_mlp_mma,  cudaFuncAttributeMaxDynamicSharedMemorySize, SMEM_M);

    k_attn_mma<<<NWIN, 128, SMEM_A>>>(x, n1g, n1b, qkvw, qkvb, relb, pw, pb);
    k_mlp_mma<<<NPIX/128, 256, SMEM_M>>>(n2g, n2b, w1, b1, w2, b2, out);
}

// round 13
// speedup vs baseline: 5.5134x; 1.2210x over previous
#include <cuda_runtime.h>
#include <cuda_bf16.h>
#include <math.h>
#include <stdint.h>

// Problem constants
#define BB 8
#define HH 256
#define WW2 256
#define CDIM 96
#define NHEAD 4
#define HD 24
#define WS 8
#define NTOK 64
#define SHIFT 4
#define NWIN 8192     // B * 32 * 32
#define NPIX (BB*HH*WW2)

// scratch: x1 = shortcut + attention branch
static __device__ float g_x1[(size_t)BB*HH*WW2*CDIM];

// pre-packed bf16-pair weights, laid out exactly as staged into smem
// qkv: [ch<3][n<96][kp<48], pw: [n<96][kp<48]
// w1:  [c<6][n<64][kp<48],  w2: [c<6][n<96][kp<32]
static __device__ uint4 g_wq4 [3*96*48/4];
static __device__ uint4 g_wp4 [96*48/4];
static __device__ uint4 g_w1p4[6*64*48/4];
static __device__ uint4 g_w2p4[6*96*32/4];

// bf16 mma m16n8k16 (portable PTX, runs on HMMA)
__device__ __forceinline__ void mma_bf16(float* d, uint32_t a0, uint32_t a1,
                                         uint32_t a2, uint32_t a3,
                                         uint32_t b0, uint32_t b1) {
    asm volatile(
        "mma.sync.aligned.m16n8k16.row.col.f32.bf16.bf16.f32 "
        "{%0,%1,%2,%3}, {%4,%5,%6,%7}, {%8,%9}, {%0,%1,%2,%3};"
        : "+f"(d[0]), "+f"(d[1]), "+f"(d[2]), "+f"(d[3])
        : "r"(a0), "r"(a1), "r"(a2), "r"(a3), "r"(b0), "r"(b1));
}

__device__ __forceinline__ void ldsm_x4(uint32_t& r0, uint32_t& r1,
                                        uint32_t& r2, uint32_t& r3, uint32_t saddr) {
    asm volatile("ldmatrix.sync.aligned.m8n8.x4.shared.b16 {%0,%1,%2,%3}, [%4];"
                 : "=r"(r0), "=r"(r1), "=r"(r2), "=r"(r3) : "r"(saddr));
}
__device__ __forceinline__ void ldsm_x2(uint32_t& r0, uint32_t& r1, uint32_t saddr) {
    asm volatile("ldmatrix.sync.aligned.m8n8.x2.shared.b16 {%0,%1}, [%2];"
                 : "=r"(r0), "=r"(r1) : "r"(saddr));
}

__device__ __forceinline__ uint32_t pack_bf16(float lo, float hi) {
    __nv_bfloat162 v = __floats2bfloat162_rn(lo, hi);
    return *(uint32_t*)&v;
}

// ===========================================================================
// k_attn_mma smem layout (u32 units). 1 window (64 tokens) per block.
// ===========================================================================
#define AQ_SB   0
#define AQ_W    904
#define AQ_A    (AQ_W + 96*52)
#define AQ_Q    (AQ_A + 64*52)
#define AQ_K    (AQ_Q + 64*68)
#define AQ_V    (AQ_K + 64*68)
#define SMEM_A_U32 (AQ_V + 96*36)
#define SMEM_A (SMEM_A_U32*4)

// ===========================================================================
// k_mlp_mma smem layout (u32 units)
// ===========================================================================
#define SB1_O  0
#define SB2_O  384
#define A_O    512
#define H_O    (A_O + 128*52)
#define W1_O   (H_O + 128*36)
#define W2_O   (W1_O + 64*52)
#define SMEM_M_U32 (W2_O + 96*36)
#define SMEM_M (SMEM_M_U32*4)

// ---------------------------------------------------------------------------
// Weight pre-pack kernel (one-time per launch, ~55K elements)
// ---------------------------------------------------------------------------
#define PACK_N (13824 + 4608 + 18432 + 18432)
__global__ void k_pack(const float* __restrict__ qkvw, const float* __restrict__ pw,
                       const float* __restrict__ w1,   const float* __restrict__ w2)
{
    int i = blockIdx.x*256 + threadIdx.x;
    if (i < 13824) {                       // qkv: [ch][n][kp]
        const int kp = i % 48, r = i / 48;
        const int ch = r / 96, n = r - 96*ch;
        ((uint32_t*)g_wq4)[i] = pack_bf16(qkvw[(size_t)(2*kp)*288 + ch*96 + n],
                                          qkvw[(size_t)(2*kp+1)*288 + ch*96 + n]);
    } else if (i < 18432) {                // pw: [n][kp]
        const int j = i - 13824;
        const int kp = j % 48, n = j / 48;
        ((uint32_t*)g_wp4)[j] = pack_bf16(pw[(size_t)(2*kp)*96 + n],
                                          pw[(size_t)(2*kp+1)*96 + n]);
    } else if (i < 36864) {                // w1: [c][n][kp]
        const int j = i - 18432;
        const int kp = j % 48, r = j / 48;
        const int c = r / 64, n = r - 64*c;
        ((uint32_t*)g_w1p4)[j] = pack_bf16(w1[(size_t)(2*kp)*384   + c*64 + n],
                                           w1[(size_t)(2*kp+1)*384 + c*64 + n]);
    } else if (i < PACK_N) {               // w2: [c][n][kp]
        const int j = i - 36864;
        const int kp = j % 32, r = j / 32;
        const int c = r / 96, n = r - 96*c;
        ((uint32_t*)g_w2p4)[j] = pack_bf16(w2[(size_t)(c*64+2*kp)*96   + n],
                                           w2[(size_t)(c*64+2*kp+1)*96 + n]);
    }
}

// ---------------------------------------------------------------------------
// Kernel 1 (HMMA): per-window LN1 + shift + QKV + attention + proj + residual
// ---------------------------------------------------------------------------
__global__ __launch_bounds__(128, 2) void k_attn_mma(
    const float* __restrict__ x,
    const float* __restrict__ n1g, const float* __restrict__ n1b,
    const float* __restrict__ qkvb,
    const float* __restrict__ relb,
    const float* __restrict__ pb)
{
    extern __shared__ uint32_t smu[];
    float*    sbias = (float*)(smu + AQ_SB);
    uint32_t* Ws  = smu + AQ_W;
    uint32_t* A32 = smu + AQ_A;   // aliased as O after QKV phase
    uint32_t* Q32 = smu + AQ_Q;
    uint32_t* K32 = smu + AQ_K;
    uint32_t* VT  = smu + AQ_V;

    const int t    = threadIdx.x;
    const int wid  = t >> 5;
    const int lane = t & 31;
    const int g    = lane >> 2;
    const int tig  = lane & 3;
    const int r0   = wid * 16;

    // ldmatrix per-lane address components
    const uint32_t lrow  = lane & 15;                       // A rows
    const uint32_t lhi16 = ((lane >> 4) & 1) * 16;          // A k+8 half
    const uint32_t brow  = (lane & 7) + ((lane >> 4) << 3); // B x4: rows + ntile pair
    const uint32_t bhi16 = ((lane >> 3) & 1) * 16;          // B k+8 half

    const uint32_t As = (uint32_t)__cvta_generic_to_shared(A32);
    const uint32_t Qs = (uint32_t)__cvta_generic_to_shared(Q32);
    const uint32_t Ks = (uint32_t)__cvta_generic_to_shared(K32);
    const uint32_t Vs = (uint32_t)__cvta_generic_to_shared(VT);
    const uint32_t Wb = (uint32_t)__cvta_generic_to_shared(Ws);

    const int win = blockIdx.x;
    const int b   = win >> 10;
    const int wr  = win & 1023;
    const int wh  = wr >> 5;
    const int ww  = wr & 31;
    const bool edgeH = (wh == 31), edgeW = (ww == 31);
    const float SCALE = rsqrtf((float)HD);

    // clipped rel-bias LUT
    for (int e = t; e < 900; e += 128) {
        const int h = e / 225, idx = e - h*225;
        float bv = relb[idx*NHEAD + h];
        sbias[e] = fminf(fmaxf(bv, -5.f), 5.f);
    }
    // zero per-head k-pad pairs (12..15) in Q32/K32
    for (int i = t; i < 64*16; i += 128) {
        const int row = i >> 4, q = i & 15;
        const int idx = row*68 + (q >> 2)*16 + 12 + (q & 3);
        Q32[idx] = 0; K32[idx] = 0;
    }

    // ---- LN1 with cyclic-shift gather -> A32 bf16 (2 threads/row) ----
    {
        const int row = t >> 1, q = t & 1;
        const int i = row >> 3, j = row & 7;
        const int h0 = (wh*8 + i + SHIFT) & 255;
        const int w0 = (ww*8 + j + SHIFT) & 255;
        const float* xr = x + (((size_t)b*HH + h0)*WW2 + w0)*CDIM + q*48;
        float v[48];
        float s1 = 0.f, s2 = 0.f;
#pragma unroll
        for (int k = 0; k < 12; k++) {
            float4 f = ((const float4*)xr)[k];
            v[4*k+0]=f.x; v[4*k+1]=f.y; v[4*k+2]=f.z; v[4*k+3]=f.w;
            s1 += f.x+f.y+f.z+f.w;
            s2 += f.x*f.x+f.y*f.y+f.z*f.z+f.w*f.w;
        }
        s1 += __shfl_xor_sync(0xffffffffu, s1, 1);
        s2 += __shfl_xor_sync(0xffffffffu, s2, 1);
        const float mean = s1 * (1.f/96.f);
        const float var  = s2 * (1.f/96.f) - mean*mean;
        const float rstd = rsqrtf(var + 1e-5f);
#pragma unroll
        for (int k = 0; k < 24; k++) {
            const int c = q*48 + 2*k;
            float a0 = (v[2*k]   - mean)*rstd*n1g[c]   + n1b[c];
            float a1 = (v[2*k+1] - mean)*rstd*n1g[c+1] + n1b[c+1];
            A32[row*52 + q*24 + k] = pack_bf16(a0, a1);
        }
    }

    // ---- QKV: 3 chunk GEMMs (Q, K, V), each [64x96] @ [96x96]^T ----
    for (int ch = 0; ch < 3; ch++) {
        __syncthreads();   // previous Ws consumed / A32 ready
        // stage pre-packed weights: 96 rows x 12 uint4
        {
            const uint4* src = g_wq4 + ch*(96*48/4);
#pragma unroll
            for (int i = 0; i < 9; i++) {
                const int e = t + 128*i;              // e < 1152
                const int n = e / 12, q = e - 12*n;
                *((uint4*)(Ws + n*52) + q) = src[e];
            }
        }
        __syncthreads();

        float d1[12][4];
#pragma unroll
        for (int nt = 0; nt < 12; nt++)
#pragma unroll
            for (int i = 0; i < 4; i++) d1[nt][i] = 0.f;
#pragma unroll
        for (int s = 0; s < 6; s++) {
            uint32_t a0, a1, a2, a3;
            ldsm_x4(a0, a1, a2, a3, As + ((r0+lrow)*52)*4 + lhi16 + s*32);
            const uint32_t bb = Wb + (brow*52)*4 + bhi16 + s*32;
#pragma unroll
            for (int np = 0; np < 6; np++) {
                uint32_t b0, b1, b2, b3;
                ldsm_x4(b0, b1, b2, b3, bb + np*(16*52*4));
                mma_bf16(d1[2*np],   a0, a1, a2, a3, b0, b1);
                mma_bf16(d1[2*np+1], a0, a1, a2, a3, b2, b3);
            }
        }

        const int c0 = ch * 96;
        if (ch < 2) {
            uint32_t* DST = (ch == 0) ? Q32 : K32;
            const float scl = (ch == 0) ? SCALE : 1.f;
#pragma unroll
            for (int nt = 0; nt < 12; nt++) {
                const int c = 8*nt + 2*tig;
                const int h = c / 24, dd = c - 24*h;
                const float bb0 = __ldg(qkvb + c0 + c), bb1 = __ldg(qkvb + c0 + c + 1);
                DST[(r0+g)*68   + h*16 + (dd>>1)] =
                    pack_bf16((d1[nt][0]+bb0)*scl, (d1[nt][1]+bb1)*scl);
                DST[(r0+g+8)*68 + h*16 + (dd>>1)] =
                    pack_bf16((d1[nt][2]+bb0)*scl, (d1[nt][3]+bb1)*scl);
            }
        } else {
            // V transposed: VT[c][token]
#pragma unroll
            for (int nt = 0; nt < 12; nt++) {
                const int c = 8*nt + 2*tig;
                const float bb0 = __ldg(qkvb + c0 + c), bb1 = __ldg(qkvb + c0 + c + 1);
                __nv_bfloat16* v0p = (__nv_bfloat16*)(VT + (size_t)c*36);
                __nv_bfloat16* v1p = (__nv_bfloat16*)(VT + (size_t)(c+1)*36);
                v0p[r0+g]   = __float2bfloat16(d1[nt][0] + bb0);
                v1p[r0+g]   = __float2bfloat16(d1[nt][1] + bb1);
                v0p[r0+g+8] = __float2bfloat16(d1[nt][2] + bb0);
                v1p[r0+g+8] = __float2bfloat16(d1[nt][3] + bb1);
            }
        }
    }
    __syncthreads();   // Q/K/VT complete; A32 now dead -> reuse as O

    // ---- attention: warp = head ----
    {
        const int h  = wid;
#pragma unroll
        for (int m = 0; m < 4; m++) {
            const int rA = m*16;
            float d[8][4];
#pragma unroll
            for (int nt = 0; nt < 8; nt++)
#pragma unroll
                for (int i = 0; i < 4; i++) d[nt][i] = 0.f;

            // scores = Q @ K^T  (2 k-steps; pads are zero)
#pragma unroll
            for (int s = 0; s < 2; s++) {
                uint32_t a0, a1, a2, a3;
                ldsm_x4(a0, a1, a2, a3,
                        Qs + ((rA+lrow)*68)*4 + h*64 + lhi16 + s*32);
                const uint32_t bb = Ks + (brow*68)*4 + h*64 + bhi16 + s*32;
#pragma unroll
                for (int np = 0; np < 4; np++) {
                    uint32_t b0, b1, b2, b3;
                    ldsm_x4(b0, b1, b2, b3, bb + np*(16*68*4));
                    mma_bf16(d[2*np],   a0, a1, a2, a3, b0, b1);
                    mma_bf16(d[2*np+1], a0, a1, a2, a3, b2, b3);
                }
            }

            // mask + bias + clip
            const int n1a = rA + g, n1b2 = rA + g + 8;
            const int i1a = n1a >> 3, j1a = n1a & 7;
            const int i1b = n1b2 >> 3, j1b = n1b2 & 7;
            const int r1a = (edgeH ? ((i1a < 4) ? 1 : 2) : 0)*3 + (edgeW ? ((j1a < 4) ? 1 : 2) : 0);
            const int r1b = (edgeH ? ((i1b < 4) ? 1 : 2) : 0)*3 + (edgeW ? ((j1b < 4) ? 1 : 2) : 0);
#pragma unroll
            for (int nt = 0; nt < 8; nt++) {
#pragma unroll
                for (int e = 0; e < 2; e++) {
                    const int cc = nt*8 + 2*tig + e;
                    const int i2 = cc >> 3, j2 = cc & 7;
                    const int r2 = (edgeH ? ((i2 < 4) ? 1 : 2) : 0)*3 + (edgeW ? ((j2 < 4) ? 1 : 2) : 0);
                    const float ba = sbias[h*225 + (i1a-i2+7)*15 + (j1a-j2+7)];
                    const float bbv = sbias[h*225 + (i1b-i2+7)*15 + (j1b-j2+7)];
                    float va = d[nt][e]   + ((r1a == r2) ? 0.f : -1e9f) + ba;
                    float vb = d[nt][e+2] + ((r1b == r2) ? 0.f : -1e9f) + bbv;
                    d[nt][e]   = fminf(fmaxf(va, -10.f), 10.f);
                    d[nt][e+2] = fminf(fmaxf(vb, -10.f), 10.f);
                }
            }

            // softmax (rows g and g+8, reduced over tig quad)
            float mx0 = -1e30f, mx1 = -1e30f;
#pragma unroll
            for (int nt = 0; nt < 8; nt++) {
                mx0 = fmaxf(mx0, fmaxf(d[nt][0], d[nt][1]));
                mx1 = fmaxf(mx1, fmaxf(d[nt][2], d[nt][3]));
            }
            mx0 = fmaxf(mx0, __shfl_xor_sync(0xffffffffu, mx0, 1));
            mx1 = fmaxf(mx1, __shfl_xor_sync(0xffffffffu, mx1, 1));
            mx0 = fmaxf(mx0, __shfl_xor_sync(0xffffffffu, mx0, 2));
            mx1 = fmaxf(mx1, __shfl_xor_sync(0xffffffffu, mx1, 2));
            float sm0 = 0.f, sm1 = 0.f;
#pragma unroll
            for (int nt = 0; nt < 8; nt++) {
                d[nt][0] = __expf(d[nt][0] - mx0); sm0 += d[nt][0];
                d[nt][1] = __expf(d[nt][1] - mx0); sm0 += d[nt][1];
                d[nt][2] = __expf(d[nt][2] - mx1); sm1 += d[nt][2];
                d[nt][3] = __expf(d[nt][3] - mx1); sm1 += d[nt][3];
            }
            sm0 += __shfl_xor_sync(0xffffffffu, sm0, 1);
            sm1 += __shfl_xor_sync(0xffffffffu, sm1, 1);
            sm0 += __shfl_xor_sync(0xffffffffu, sm0, 2);
            sm1 += __shfl_xor_sync(0xffffffffu, sm1, 2);
            const float inv0 = 1.f / sm0, inv1 = 1.f / sm1;
#pragma unroll
            for (int nt = 0; nt < 8; nt++) {
                d[nt][0] *= inv0; d[nt][1] *= inv0;
                d[nt][2] *= inv1; d[nt][3] *= inv1;
            }

            // AV: P (regs -> A frags) @ VT
            float oacc[3][4];
#pragma unroll
            for (int vt = 0; vt < 3; vt++)
#pragma unroll
                for (int i = 0; i < 4; i++) oacc[vt][i] = 0.f;
#pragma unroll
            for (int s = 0; s < 4; s++) {
                uint32_t a0 = pack_bf16(d[2*s][0],   d[2*s][1]);
                uint32_t a1 = pack_bf16(d[2*s][2],   d[2*s][3]);
                uint32_t a2 = pack_bf16(d[2*s+1][0], d[2*s+1][1]);
                uint32_t a3 = pack_bf16(d[2*s+1][2], d[2*s+1][3]);
                {
                    uint32_t b0, b1, b2, b3;
                    ldsm_x4(b0, b1, b2, b3,
                            Vs + ((h*24 + brow)*36)*4 + bhi16 + s*32);
                    mma_bf16(oacc[0], a0, a1, a2, a3, b0, b1);
                    mma_bf16(oacc[1], a0, a1, a2, a3, b2, b3);
                }
                {
                    uint32_t b0, b1;
                    ldsm_x2(b0, b1,
                            Vs + ((h*24 + 16 + (lane & 7))*36)*4 + bhi16 + s*32);
                    mma_bf16(oacc[2], a0, a1, a2, a3, b0, b1);
                }
            }
            // write O (aliases A32): col = h*24 + vt*8 + 2tig
#pragma unroll
            for (int vt = 0; vt < 3; vt++) {
                const int pi = h*12 + vt*4 + tig;
                A32[(rA+g)*52   + pi] = pack_bf16(oacc[vt][0], oacc[vt][1]);
                A32[(rA+g+8)*52 + pi] = pack_bf16(oacc[vt][2], oacc[vt][3]);
            }
        }
    }
    __syncthreads();   // O complete, Ws (V chunk) consumed

    // ---- proj: O[64x96] @ pw^T + un-shift residual -> g_x1 ----
#pragma unroll
    for (int i = 0; i < 9; i++) {
        const int e = t + 128*i;
        const int n = e / 12, q = e - 12*n;
        *((uint4*)(Ws + n*52) + q) = g_wp4[e];
    }
    __syncthreads();
    {
        float d2[12][4];
#pragma unroll
        for (int nt = 0; nt < 12; nt++)
#pragma unroll
            for (int i = 0; i < 4; i++) d2[nt][i] = 0.f;
#pragma unroll
        for (int s = 0; s < 6; s++) {
            uint32_t a0, a1, a2, a3;
            ldsm_x4(a0, a1, a2, a3, As + ((r0+lrow)*52)*4 + lhi16 + s*32);
            const uint32_t bb = Wb + (brow*52)*4 + bhi16 + s*32;
#pragma unroll
            for (int np = 0; np < 6; np++) {
                uint32_t b0, b1, b2, b3;
                ldsm_x4(b0, b1, b2, b3, bb + np*(16*52*4));
                mma_bf16(d2[2*np],   a0, a1, a2, a3, b0, b1);
                mma_bf16(d2[2*np+1], a0, a1, a2, a3, b2, b3);
            }
        }
        // epilogue: un-shift + residual
        const int ra = r0 + g, rb2 = r0 + g + 8;
        const int ia = ra >> 3, ja = ra & 7;
        const int ib = rb2 >> 3, jb = rb2 & 7;
        const size_t basea = (((size_t)b*HH + ((wh*8 + ia + SHIFT) & 255))*WW2
                              + ((ww*8 + ja + SHIFT) & 255))*CDIM;
        const size_t baseb = (((size_t)b*HH + ((wh*8 + ib + SHIFT) & 255))*WW2
                              + ((ww*8 + jb + SHIFT) & 255))*CDIM;
#pragma unroll
        for (int nt = 0; nt < 12; nt++) {
            const int c = 8*nt + 2*tig;
            const float p0v = __ldg(pb + c), p1v = __ldg(pb + c + 1);
            float2 xa = *(const float2*)(x + basea + c);
            float2 xb = *(const float2*)(x + baseb + c);
            float2 oa, ob;
            oa.x = xa.x + d2[nt][0] + p0v;
            oa.y = xa.y + d2[nt][1] + p1v;
            ob.x = xb.x + d2[nt][2] + p0v;
            ob.y = xb.y + d2[nt][3] + p1v;
            *(float2*)(g_x1 + basea + c) = oa;
            *(float2*)(g_x1 + baseb + c) = ob;
        }
    }
}

// ---------------------------------------------------------------------------
// Kernel 2 (HMMA): 128 pixels/block  LN2 + MLP + residual
// ---------------------------------------------------------------------------
__global__ __launch_bounds__(256, 2) void k_mlp_mma(
    const float* __restrict__ n2g, const float* __restrict__ n2b,
    const float* __restrict__ b1,  const float* __restrict__ b2,
    float* __restrict__ out)
{
    extern __shared__ uint32_t smu[];
    float*    sb1 = (float*)(smu + SB1_O);
    float*    sb2 = (float*)(smu + SB2_O);
    uint32_t* A32 = smu + A_O;
    uint32_t* H32 = smu + H_O;
    uint32_t* W1s = smu + W1_O;
    uint32_t* W2s = smu + W2_O;

    const int t    = threadIdx.x;
    const int wid  = t >> 5;
    const int lane = t & 31;
    const int g    = lane >> 2;
    const int tig  = lane & 3;
    const int r0   = wid * 16;
    const size_t p0 = (size_t)blockIdx.x * 128;

    const uint32_t lrow  = lane & 15;
    const uint32_t lhi16 = ((lane >> 4) & 1) * 16;
    const uint32_t brow  = (lane & 7) + ((lane >> 4) << 3);
    const uint32_t bhi16 = ((lane >> 3) & 1) * 16;

    const uint32_t As  = (uint32_t)__cvta_generic_to_shared(A32);
    const uint32_t Hs  = (uint32_t)__cvta_generic_to_shared(H32);
    const uint32_t W1b = (uint32_t)__cvta_generic_to_shared(W1s);
    const uint32_t W2b = (uint32_t)__cvta_generic_to_shared(W2s);

    for (int i = t; i < 384; i += 256) sb1[i] = b1[i];
    if (t < 96) sb2[t] = b2[t];

    {
        const int row = t >> 1, q = t & 1;
        const float* xr = g_x1 + (p0 + row)*96 + q*48;
        float v[48];
        float s1 = 0.f, s2 = 0.f;
#pragma unroll
        for (int k = 0; k < 12; k++) {
            float4 f = ((const float4*)xr)[k];
            v[4*k+0]=f.x; v[4*k+1]=f.y; v[4*k+2]=f.z; v[4*k+3]=f.w;
            s1 += f.x+f.y+f.z+f.w;
            s2 += f.x*f.x+f.y*f.y+f.z*f.z+f.w*f.w;
        }
        s1 += __shfl_xor_sync(0xffffffffu, s1, 1);
        s2 += __shfl_xor_sync(0xffffffffu, s2, 1);
        const float mean = s1 * (1.f/96.f);
        const float var  = s2 * (1.f/96.f) - mean*mean;
        const float rstd = rsqrtf(var + 1e-5f);
#pragma unroll
        for (int k = 0; k < 24; k++) {
            const int c = q*48 + 2*k;
            float a0 = (v[2*k]   - mean)*rstd*n2g[c]   + n2b[c];
            float a1 = (v[2*k+1] - mean)*rstd*n2g[c+1] + n2b[c+1];
            A32[row*52 + q*24 + k] = pack_bf16(a0, a1);
        }
    }

    float d2[12][4];
#pragma unroll
    for (int nt = 0; nt < 12; nt++)
#pragma unroll
        for (int i = 0; i < 4; i++) d2[nt][i] = 0.f;

    for (int c = 0; c < 6; c++) {
        const int co0 = c*64;
        __syncthreads();

        // stage pre-packed weights: w1 chunk 64x12 uint4, w2 chunk 96x8 uint4
        {
            const uint4* s1p = g_w1p4 + c*(64*48/4);
#pragma unroll
            for (int i = 0; i < 3; i++) {
                const int e = t + 256*i;              // e < 768
                const int n = e / 12, q = e - 12*n;
                *((uint4*)(W1s + n*52) + q) = s1p[e];
            }
            const uint4* s2p = g_w2p4 + c*(96*32/4);
#pragma unroll
            for (int i = 0; i < 3; i++) {
                const int e = t + 256*i;              // e < 768
                const int n = e >> 3, q = e & 7;
                *((uint4*)(W2s + n*36) + q) = s2p[e];
            }
        }
        __syncthreads();

        float d1[8][4];
#pragma unroll
        for (int nt = 0; nt < 8; nt++)
#pragma unroll
            for (int i = 0; i < 4; i++) d1[nt][i] = 0.f;

#pragma unroll
        for (int s = 0; s < 6; s++) {
            uint32_t a0, a1, a2, a3;
            ldsm_x4(a0, a1, a2, a3, As + ((r0+lrow)*52)*4 + lhi16 + s*32);
            const uint32_t bb = W1b + (brow*52)*4 + bhi16 + s*32;
#pragma unroll
            for (int np = 0; np < 4; np++) {
                uint32_t b0, b1, b2, b3;
                ldsm_x4(b0, b1, b2, b3, bb + np*(16*52*4));
                mma_bf16(d1[2*np],   a0, a1, a2, a3, b0, b1);
                mma_bf16(d1[2*np+1], a0, a1, a2, a3, b2, b3);
            }
        }

#pragma unroll
        for (int nt = 0; nt < 8; nt++) {
            const int cn = nt*8 + 2*tig;
            const float bb0 = sb1[co0 + cn], bb1 = sb1[co0 + cn + 1];
            float v0 = d1[nt][0] + bb0, v1 = d1[nt][1] + bb1;
            float v2 = d1[nt][2] + bb0, v3 = d1[nt][3] + bb1;
            v0 = 0.5f*v0*(1.f + erff(v0*0.7071067811865476f));
            v1 = 0.5f*v1*(1.f + erff(v1*0.7071067811865476f));
            v2 = 0.5f*v2*(1.f + erff(v2*0.7071067811865476f));
            v3 = 0.5f*v3*(1.f + erff(v3*0.7071067811865476f));
            H32[(r0+g)*36   + nt*4 + tig] = pack_bf16(v0, v1);
            H32[(r0+g+8)*36 + nt*4 + tig] = pack_bf16(v2, v3);
        }
        __syncwarp();

#pragma unroll
        for (int s = 0; s < 4; s++) {
            uint32_t a0, a1, a2, a3;
            ldsm_x4(a0, a1, a2, a3, Hs + ((r0+lrow)*36)*4 + lhi16 + s*32);
            const uint32_t bb = W2b + (brow*36)*4 + bhi16 + s*32;
#pragma unroll
            for (int np = 0; np < 6; np++) {
                uint32_t b0, b1, b2, b3;
                ldsm_x4(b0, b1, b2, b3, bb + np*(16*36*4));
                mma_bf16(d2[2*np],   a0, a1, a2, a3, b0, b1);
                mma_bf16(d2[2*np+1], a0, a1, a2, a3, b2, b3);
            }
        }
    }

#pragma unroll
    for (int nt = 0; nt < 12; nt++) {
        const int col = nt*8 + 2*tig;
        const float bb0 = sb2[col], bb1 = sb2[col + 1];
        const size_t i0 = (p0 + r0 + g)*96 + col;
        const size_t i1 = (p0 + r0 + g + 8)*96 + col;
        float2 x0 = *(const float2*)(g_x1 + i0);
        float2 x1v = *(const float2*)(g_x1 + i1);
        float2 o0, o1;
        o0.x = x0.x + d2[nt][0] + bb0;
        o0.y = x0.y + d2[nt][1] + bb1;
        o1.x = x1v.x + d2[nt][2] + bb0;
        o1.y = x1v.y + d2[nt][3] + bb1;
        *(float2*)(out + i0) = o0;
        *(float2*)(out + i1) = o1;
    }
}

// ---------------------------------------------------------------------------
extern "C" void kernel_launch(void* const* d_in, const int* in_sizes, int n_in,
                              void* d_out, int out_size)
{
    const float* x    = (const float*)d_in[0];
    const float* n1g  = (const float*)d_in[1];
    const float* n1b  = (const float*)d_in[2];
    const float* qkvw = (const float*)d_in[3];
    const float* qkvb = (const float*)d_in[4];
    const float* relb = (const float*)d_in[5];
    const float* pw   = (const float*)d_in[6];
    const float* pb   = (const float*)d_in[7];
    const float* n2g  = (const float*)d_in[8];
    const float* n2b  = (const float*)d_in[9];
    const float* w1   = (const float*)d_in[10];
    const float* b1   = (const float*)d_in[11];
    const float* w2   = (const float*)d_in[12];
    const float* b2   = (const float*)d_in[13];
    float* out = (float*)d_out;

    cudaFuncSetAttribute(k_attn_mma, cudaFuncAttributeMaxDynamicSharedMemorySize, SMEM_A);
    cudaFuncSetAttribute(k_mlp_mma,  cudaFuncAttributeMaxDynamicSharedMemorySize, SMEM_M);

    k_pack<<<(PACK_N + 255)/256, 256>>>(qkvw, pw, w1, w2);
    k_attn_mma<<<NWIN, 128, SMEM_A>>>(x, n1g, n1b, qkvb, relb, pb);
    k_mlp_mma<<<NPIX/128, 256, SMEM_M>>>(n2g, n2b, b1, b2, out);
}

// round 14
// speedup vs baseline: 5.5436x; 1.0055x over previous
#include <cuda_runtime.h>
#include <cuda_bf16.h>
#include <math.h>
#include <stdint.h>

// Problem constants
#define BB 8
#define HH 256
#define WW2 256
#define CDIM 96
#define NHEAD 4
#define HD 24
#define WS 8
#define NTOK 64
#define SHIFT 4
#define NWIN 8192     // B * 32 * 32
#define NPIX (BB*HH*WW2)

// scratch: x1 = shortcut + attention branch
static __device__ float g_x1[(size_t)BB*HH*WW2*CDIM];

// pre-packed bf16-pair weights, laid out exactly as staged into smem
static __device__ uint4 g_wq4 [3*96*48/4];
static __device__ uint4 g_wp4 [96*48/4];
static __device__ uint4 g_w1p4[6*64*48/4];
static __device__ uint4 g_w2p4[6*96*32/4];

// bf16 mma m16n8k16 (portable PTX, runs on HMMA)
__device__ __forceinline__ void mma_bf16(float* d, uint32_t a0, uint32_t a1,
                                         uint32_t a2, uint32_t a3,
                                         uint32_t b0, uint32_t b1) {
    asm volatile(
        "mma.sync.aligned.m16n8k16.row.col.f32.bf16.bf16.f32 "
        "{%0,%1,%2,%3}, {%4,%5,%6,%7}, {%8,%9}, {%0,%1,%2,%3};"
        : "+f"(d[0]), "+f"(d[1]), "+f"(d[2]), "+f"(d[3])
        : "r"(a0), "r"(a1), "r"(a2), "r"(a3), "r"(b0), "r"(b1));
}

__device__ __forceinline__ void ldsm_x4(uint32_t& r0, uint32_t& r1,
                                        uint32_t& r2, uint32_t& r3, uint32_t saddr) {
    asm volatile("ldmatrix.sync.aligned.m8n8.x4.shared.b16 {%0,%1,%2,%3}, [%4];"
                 : "=r"(r0), "=r"(r1), "=r"(r2), "=r"(r3) : "r"(saddr));
}
__device__ __forceinline__ void ldsm_x2(uint32_t& r0, uint32_t& r1, uint32_t saddr) {
    asm volatile("ldmatrix.sync.aligned.m8n8.x2.shared.b16 {%0,%1}, [%2];"
                 : "=r"(r0), "=r"(r1) : "r"(saddr));
}

__device__ __forceinline__ uint32_t pack_bf16(float lo, float hi) {
    __nv_bfloat162 v = __floats2bfloat162_rn(lo, hi);
    return *(uint32_t*)&v;
}

// cp.async 16B (LDGSTS)
__device__ __forceinline__ void cp_async16(uint32_t saddr, const void* g) {
    asm volatile("cp.async.cg.shared.global [%0], [%1], 16;"
                 :: "r"(saddr), "l"(__cvta_generic_to_global(g)) : "memory");
}
#define CP_COMMIT() asm volatile("cp.async.commit_group;" ::: "memory")
#define CP_WAIT0()  asm volatile("cp.async.wait_group 0;" ::: "memory")

// ===========================================================================
// k_attn_mma smem layout (u32 units). 1 window (64 tokens) per block.
//   Ws is DOUBLE-BUFFERED (2 x 96 x 52)
// ===========================================================================
#define AQ_SB   0
#define AQ_W    904
#define AQ_A    (AQ_W + 2*96*52)
#define AQ_Q    (AQ_A + 64*52)
#define AQ_K    (AQ_Q + 64*68)
#define AQ_V    (AQ_K + 64*68)
#define SMEM_A_U32 (AQ_V + 96*36)
#define SMEM_A (SMEM_A_U32*4)     // 105504 bytes

// ===========================================================================
// k_mlp_mma smem layout (u32 units). W1s/W2s DOUBLE-BUFFERED.
// ===========================================================================
#define SB1_O  0
#define SB2_O  384
#define A_O    512
#define H_O    (A_O + 128*52)
#define W1_O   (H_O + 128*36)
#define W2_O   (W1_O + 2*64*52)
#define SMEM_M_U32 (W2_O + 2*96*36)
#define SMEM_M (SMEM_M_U32*4)     // 101376 bytes

// ---------------------------------------------------------------------------
// Weight pre-pack kernel (one-time per launch)
// ---------------------------------------------------------------------------
#define PACK_N (13824 + 4608 + 18432 + 18432)
__global__ void k_pack(const float* __restrict__ qkvw, const float* __restrict__ pw,
                       const float* __restrict__ w1,   const float* __restrict__ w2)
{
    int i = blockIdx.x*256 + threadIdx.x;
    if (i < 13824) {                       // qkv: [ch][n][kp]
        const int kp = i % 48, r = i / 48;
        const int ch = r / 96, n = r - 96*ch;
        ((uint32_t*)g_wq4)[i] = pack_bf16(qkvw[(size_t)(2*kp)*288 + ch*96 + n],
                                          qkvw[(size_t)(2*kp+1)*288 + ch*96 + n]);
    } else if (i < 18432) {                // pw: [n][kp]
        const int j = i - 13824;
        const int kp = j % 48, n = j / 48;
        ((uint32_t*)g_wp4)[j] = pack_bf16(pw[(size_t)(2*kp)*96 + n],
                                          pw[(size_t)(2*kp+1)*96 + n]);
    } else if (i < 36864) {                // w1: [c][n][kp]
        const int j = i - 18432;
        const int kp = j % 48, r = j / 48;
        const int c = r / 64, n = r - 64*c;
        ((uint32_t*)g_w1p4)[j] = pack_bf16(w1[(size_t)(2*kp)*384   + c*64 + n],
                                           w1[(size_t)(2*kp+1)*384 + c*64 + n]);
    } else if (i < PACK_N) {               // w2: [c][n][kp]
        const int j = i - 36864;
        const int kp = j % 32, r = j / 32;
        const int c = r / 96, n = r - 96*c;
        ((uint32_t*)g_w2p4)[j] = pack_bf16(w2[(size_t)(c*64+2*kp)*96   + n],
                                           w2[(size_t)(c*64+2*kp+1)*96 + n]);
    }
}

// ---------------------------------------------------------------------------
// Kernel 1 (HMMA): per-window LN1 + shift + QKV + attention + proj + residual
// ---------------------------------------------------------------------------
__global__ __launch_bounds__(128, 2) void k_attn_mma(
    const float* __restrict__ x,
    const float* __restrict__ n1g, const float* __restrict__ n1b,
    const float* __restrict__ qkvb,
    const float* __restrict__ relb,
    const float* __restrict__ pb)
{
    extern __shared__ uint32_t smu[];
    float*    sbias = (float*)(smu + AQ_SB);
    uint32_t* A32 = smu + AQ_A;   // aliased as O after QKV phase
    uint32_t* Q32 = smu + AQ_Q;
    uint32_t* K32 = smu + AQ_K;
    uint32_t* VT  = smu + AQ_V;

    const int t    = threadIdx.x;
    const int wid  = t >> 5;
    const int lane = t & 31;
    const int g    = lane >> 2;
    const int tig  = lane & 3;
    const int r0   = wid * 16;

    const uint32_t lrow  = lane & 15;
    const uint32_t lhi16 = ((lane >> 4) & 1) * 16;
    const uint32_t brow  = (lane & 7) + ((lane >> 4) << 3);
    const uint32_t bhi16 = ((lane >> 3) & 1) * 16;

    const uint32_t As = (uint32_t)__cvta_generic_to_shared(A32);
    const uint32_t Qs = (uint32_t)__cvta_generic_to_shared(Q32);
    const uint32_t Ks = (uint32_t)__cvta_generic_to_shared(K32);
    const uint32_t Vs = (uint32_t)__cvta_generic_to_shared(VT);
    const uint32_t Wb = (uint32_t)__cvta_generic_to_shared(smu + AQ_W);
    const uint32_t wbuf[2] = {Wb, Wb + 96*52*4};

    // staging: 96 rows x 12 uint4 each, row stride 52 u32
    auto stage96 = [&](uint32_t dstb, const uint4* src) {
#pragma unroll
        for (int i = 0; i < 9; i++) {
            const int e = t + 128*i;              // e < 1152
            const int n = e / 12, q = e - 12*n;
            cp_async16(dstb + (n*52 + 4*q)*4, src + e);
        }
    };

    const int win = blockIdx.x;
    const int b   = win >> 10;
    const int wr  = win & 1023;
    const int wh  = wr >> 5;
    const int ww  = wr & 31;
    const bool edgeH = (wh == 31), edgeW = (ww == 31);
    const float SCALE = rsqrtf((float)HD);

    // kick off first weight fetch before doing anything else
    stage96(wbuf[0], g_wq4);
    CP_COMMIT();

    // clipped rel-bias LUT
    for (int e = t; e < 900; e += 128) {
        const int h = e / 225, idx = e - h*225;
        float bv = relb[idx*NHEAD + h];
        sbias[e] = fminf(fmaxf(bv, -5.f), 5.f);
    }
    // zero per-head k-pad pairs (12..15) in Q32/K32
    for (int i = t; i < 64*16; i += 128) {
        const int row = i >> 4, q = i & 15;
        const int idx = row*68 + (q >> 2)*16 + 12 + (q & 3);
        Q32[idx] = 0; K32[idx] = 0;
    }

    // ---- LN1 with cyclic-shift gather -> A32 bf16 (2 threads/row) ----
    {
        const int row = t >> 1, q = t & 1;
        const int i = row >> 3, j = row & 7;
        const int h0 = (wh*8 + i + SHIFT) & 255;
        const int w0 = (ww*8 + j + SHIFT) & 255;
        const float* xr = x + (((size_t)b*HH + h0)*WW2 + w0)*CDIM + q*48;
        float v[48];
        float s1 = 0.f, s2 = 0.f;
#pragma unroll
        for (int k = 0; k < 12; k++) {
            float4 f = ((const float4*)xr)[k];
            v[4*k+0]=f.x; v[4*k+1]=f.y; v[4*k+2]=f.z; v[4*k+3]=f.w;
            s1 += f.x+f.y+f.z+f.w;
            s2 += f.x*f.x+f.y*f.y+f.z*f.z+f.w*f.w;
        }
        s1 += __shfl_xor_sync(0xffffffffu, s1, 1);
        s2 += __shfl_xor_sync(0xffffffffu, s2, 1);
        const float mean = s1 * (1.f/96.f);
        const float var  = s2 * (1.f/96.f) - mean*mean;
        const float rstd = rsqrtf(var + 1e-5f);
#pragma unroll
        for (int k = 0; k < 24; k++) {
            const int c = q*48 + 2*k;
            float a0 = (v[2*k]   - mean)*rstd*n1g[c]   + n1b[c];
            float a1 = (v[2*k+1] - mean)*rstd*n1g[c+1] + n1b[c+1];
            A32[row*52 + q*24 + k] = pack_bf16(a0, a1);
        }
    }

    // ---- QKV: 3 chunk GEMMs (Q, K, V) with double-buffered weights ----
    for (int ch = 0; ch < 3; ch++) {
        CP_WAIT0();
        __syncthreads();   // weights(ch) visible; prior readers of next buffer done
        if (ch < 2) stage96(wbuf[(ch+1)&1], g_wq4 + (ch+1)*(96*48/4));
        else        stage96(wbuf[1], g_wp4);     // proj weights, hidden under attention
        CP_COMMIT();

        const uint32_t Wcur = wbuf[ch & 1];
        float d1[12][4];
#pragma unroll
        for (int nt = 0; nt < 12; nt++)
#pragma unroll
            for (int i = 0; i < 4; i++) d1[nt][i] = 0.f;
#pragma unroll
        for (int s = 0; s < 6; s++) {
            uint32_t a0, a1, a2, a3;
            ldsm_x4(a0, a1, a2, a3, As + ((r0+lrow)*52)*4 + lhi16 + s*32);
            const uint32_t bb = Wcur + (brow*52)*4 + bhi16 + s*32;
#pragma unroll
            for (int np = 0; np < 6; np++) {
                uint32_t b0, b1, b2, b3;
                ldsm_x4(b0, b1, b2, b3, bb + np*(16*52*4));
                mma_bf16(d1[2*np],   a0, a1, a2, a3, b0, b1);
                mma_bf16(d1[2*np+1], a0, a1, a2, a3, b2, b3);
            }
        }

        const int c0 = ch * 96;
        if (ch < 2) {
            uint32_t* DST = (ch == 0) ? Q32 : K32;
            const float scl = (ch == 0) ? SCALE : 1.f;
#pragma unroll
            for (int nt = 0; nt < 12; nt++) {
                const int c = 8*nt + 2*tig;
                const int h = c / 24, dd = c - 24*h;
                const float bb0 = __ldg(qkvb + c0 + c), bb1 = __ldg(qkvb + c0 + c + 1);
                DST[(r0+g)*68   + h*16 + (dd>>1)] =
                    pack_bf16((d1[nt][0]+bb0)*scl, (d1[nt][1]+bb1)*scl);
                DST[(r0+g+8)*68 + h*16 + (dd>>1)] =
                    pack_bf16((d1[nt][2]+bb0)*scl, (d1[nt][3]+bb1)*scl);
            }
        } else {
            // V transposed: VT[c][token]
#pragma unroll
            for (int nt = 0; nt < 12; nt++) {
                const int c = 8*nt + 2*tig;
                const float bb0 = __ldg(qkvb + c0 + c), bb1 = __ldg(qkvb + c0 + c + 1);
                __nv_bfloat16* v0p = (__nv_bfloat16*)(VT + (size_t)c*36);
                __nv_bfloat16* v1p = (__nv_bfloat16*)(VT + (size_t)(c+1)*36);
                v0p[r0+g]   = __float2bfloat16(d1[nt][0] + bb0);
                v1p[r0+g]   = __float2bfloat16(d1[nt][1] + bb1);
                v0p[r0+g+8] = __float2bfloat16(d1[nt][2] + bb0);
                v1p[r0+g+8] = __float2bfloat16(d1[nt][3] + bb1);
            }
        }
    }
    __syncthreads();   // Q/K/VT complete; A32 now dead -> reuse as O

    // ---- attention: warp = head (proj weight fetch in flight underneath) ----
    {
        const int h  = wid;
#pragma unroll
        for (int m = 0; m < 4; m++) {
            const int rA = m*16;
            float d[8][4];
#pragma unroll
            for (int nt = 0; nt < 8; nt++)
#pragma unroll
                for (int i = 0; i < 4; i++) d[nt][i] = 0.f;

            // scores = Q @ K^T  (2 k-steps; pads are zero)
#pragma unroll
            for (int s = 0; s < 2; s++) {
                uint32_t a0, a1, a2, a3;
                ldsm_x4(a0, a1, a2, a3,
                        Qs + ((rA+lrow)*68)*4 + h*64 + lhi16 + s*32);
                const uint32_t bb = Ks + (brow*68)*4 + h*64 + bhi16 + s*32;
#pragma unroll
                for (int np = 0; np < 4; np++) {
                    uint32_t b0, b1, b2, b3;
                    ldsm_x4(b0, b1, b2, b3, bb + np*(16*68*4));
                    mma_bf16(d[2*np],   a0, a1, a2, a3, b0, b1);
                    mma_bf16(d[2*np+1], a0, a1, a2, a3, b2, b3);
                }
            }

            // mask + bias + clip
            const int n1a = rA + g, n1b2 = rA + g + 8;
            const int i1a = n1a >> 3, j1a = n1a & 7;
            const int i1b = n1b2 >> 3, j1b = n1b2 & 7;
            const int r1a = (edgeH ? ((i1a < 4) ? 1 : 2) : 0)*3 + (edgeW ? ((j1a < 4) ? 1 : 2) : 0);
            const int r1b = (edgeH ? ((i1b < 4) ? 1 : 2) : 0)*3 + (edgeW ? ((j1b < 4) ? 1 : 2) : 0);
#pragma unroll
            for (int nt = 0; nt < 8; nt++) {
#pragma unroll
                for (int e = 0; e < 2; e++) {
                    const int cc = nt*8 + 2*tig + e;
                    const int i2 = cc >> 3, j2 = cc & 7;
                    const int r2 = (edgeH ? ((i2 < 4) ? 1 : 2) : 0)*3 + (edgeW ? ((j2 < 4) ? 1 : 2) : 0);
                    const float ba = sbias[h*225 + (i1a-i2+7)*15 + (j1a-j2+7)];
                    const float bbv = sbias[h*225 + (i1b-i2+7)*15 + (j1b-j2+7)];
                    float va = d[nt][e]   + ((r1a == r2) ? 0.f : -1e9f) + ba;
                    float vb = d[nt][e+2] + ((r1b == r2) ? 0.f : -1e9f) + bbv;
                    d[nt][e]   = fminf(fmaxf(va, -10.f), 10.f);
                    d[nt][e+2] = fminf(fmaxf(vb, -10.f), 10.f);
                }
            }

            // softmax (rows g and g+8, reduced over tig quad)
            float mx0 = -1e30f, mx1 = -1e30f;
#pragma unroll
            for (int nt = 0; nt < 8; nt++) {
                mx0 = fmaxf(mx0, fmaxf(d[nt][0], d[nt][1]));
                mx1 = fmaxf(mx1, fmaxf(d[nt][2], d[nt][3]));
            }
            mx0 = fmaxf(mx0, __shfl_xor_sync(0xffffffffu, mx0, 1));
            mx1 = fmaxf(mx1, __shfl_xor_sync(0xffffffffu, mx1, 1));
            mx0 = fmaxf(mx0, __shfl_xor_sync(0xffffffffu, mx0, 2));
            mx1 = fmaxf(mx1, __shfl_xor_sync(0xffffffffu, mx1, 2));
            float sm0 = 0.f, sm1 = 0.f;
#pragma unroll
            for (int nt = 0; nt < 8; nt++) {
                d[nt][0] = __expf(d[nt][0] - mx0); sm0 += d[nt][0];
                d[nt][1] = __expf(d[nt][1] - mx0); sm0 += d[nt][1];
                d[nt][2] = __expf(d[nt][2] - mx1); sm1 += d[nt][2];
                d[nt][3] = __expf(d[nt][3] - mx1); sm1 += d[nt][3];
            }
            sm0 += __shfl_xor_sync(0xffffffffu, sm0, 1);
            sm1 += __shfl_xor_sync(0xffffffffu, sm1, 1);
            sm0 += __shfl_xor_sync(0xffffffffu, sm0, 2);
            sm1 += __shfl_xor_sync(0xffffffffu, sm1, 2);
            const float inv0 = 1.f / sm0, inv1 = 1.f / sm1;
#pragma unroll
            for (int nt = 0; nt < 8; nt++) {
                d[nt][0] *= inv0; d[nt][1] *= inv0;
                d[nt][2] *= inv1; d[nt][3] *= inv1;
            }

            // AV: P (regs -> A frags) @ VT
            float oacc[3][4];
#pragma unroll
            for (int vt = 0; vt < 3; vt++)
#pragma unroll
                for (int i = 0; i < 4; i++) oacc[vt][i] = 0.f;
#pragma unroll
            for (int s = 0; s < 4; s++) {
                uint32_t a0 = pack_bf16(d[2*s][0],   d[2*s][1]);
                uint32_t a1 = pack_bf16(d[2*s][2],   d[2*s][3]);
                uint32_t a2 = pack_bf16(d[2*s+1][0], d[2*s+1][1]);
                uint32_t a3 = pack_bf16(d[2*s+1][2], d[2*s+1][3]);
                {
                    uint32_t b0, b1, b2, b3;
                    ldsm_x4(b0, b1, b2, b3,
                            Vs + ((h*24 + brow)*36)*4 + bhi16 + s*32);
                    mma_bf16(oacc[0], a0, a1, a2, a3, b0, b1);
                    mma_bf16(oacc[1], a0, a1, a2, a3, b2, b3);
                }
                {
                    uint32_t b0, b1;
                    ldsm_x2(b0, b1,
                            Vs + ((h*24 + 16 + (lane & 7))*36)*4 + bhi16 + s*32);
                    mma_bf16(oacc[2], a0, a1, a2, a3, b0, b1);
                }
            }
            // write O (aliases A32): col = h*24 + vt*8 + 2tig
#pragma unroll
            for (int vt = 0; vt < 3; vt++) {
                const int pi = h*12 + vt*4 + tig;
                A32[(rA+g)*52   + pi] = pack_bf16(oacc[vt][0], oacc[vt][1]);
                A32[(rA+g+8)*52 + pi] = pack_bf16(oacc[vt][2], oacc[vt][3]);
            }
        }
    }
    CP_WAIT0();        // proj weights landed long ago
    __syncthreads();   // O complete + proj weights visible

    // ---- proj: O[64x96] @ pw^T + un-shift residual -> g_x1 ----
    {
        const uint32_t Wcur = wbuf[1];
        float d2[12][4];
#pragma unroll
        for (int nt = 0; nt < 12; nt++)
#pragma unroll
            for (int i = 0; i < 4; i++) d2[nt][i] = 0.f;
#pragma unroll
        for (int s = 0; s < 6; s++) {
            uint32_t a0, a1, a2, a3;
            ldsm_x4(a0, a1, a2, a3, As + ((r0+lrow)*52)*4 + lhi16 + s*32);
            const uint32_t bb = Wcur + (brow*52)*4 + bhi16 + s*32;
#pragma unroll
            for (int np = 0; np < 6; np++) {
                uint32_t b0, b1, b2, b3;
                ldsm_x4(b0, b1, b2, b3, bb + np*(16*52*4));
                mma_bf16(d2[2*np],   a0, a1, a2, a3, b0, b1);
                mma_bf16(d2[2*np+1], a0, a1, a2, a3, b2, b3);
            }
        }
        // epilogue: un-shift + residual
        const int ra = r0 + g, rb2 = r0 + g + 8;
        const int ia = ra >> 3, ja = ra & 7;
        const int ib = rb2 >> 3, jb = rb2 & 7;
        const size_t basea = (((size_t)b*HH + ((wh*8 + ia + SHIFT) & 255))*WW2
                              + ((ww*8 + ja + SHIFT) & 255))*CDIM;
        const size_t baseb = (((size_t)b*HH + ((wh*8 + ib + SHIFT) & 255))*WW2
                              + ((ww*8 + jb + SHIFT) & 255))*CDIM;
#pragma unroll
        for (int nt = 0; nt < 12; nt++) {
            const int c = 8*nt + 2*tig;
            const float p0v = __ldg(pb + c), p1v = __ldg(pb + c + 1);
            float2 xa = *(const float2*)(x + basea + c);
            float2 xb = *(const float2*)(x + baseb + c);
            float2 oa, ob;
            oa.x = xa.x + d2[nt][0] + p0v;
            oa.y = xa.y + d2[nt][1] + p1v;
            ob.x = xb.x + d2[nt][2] + p0v;
            ob.y = xb.y + d2[nt][3] + p1v;
            *(float2*)(g_x1 + basea + c) = oa;
            *(float2*)(g_x1 + baseb + c) = ob;
        }
    }
}

// ---------------------------------------------------------------------------
// Kernel 2 (HMMA): 128 pixels/block  LN2 + MLP + residual, double-buffered
// ---------------------------------------------------------------------------
__global__ __launch_bounds__(256, 2) void k_mlp_mma(
    const float* __restrict__ n2g, const float* __restrict__ n2b,
    const float* __restrict__ b1,  const float* __restrict__ b2,
    float* __restrict__ out)
{
    extern __shared__ uint32_t smu[];
    float*    sb1 = (float*)(smu + SB1_O);
    float*    sb2 = (float*)(smu + SB2_O);
    uint32_t* A32 = smu + A_O;
    uint32_t* H32 = smu + H_O;

    const int t    = threadIdx.x;
    const int wid  = t >> 5;
    const int lane = t & 31;
    const int g    = lane >> 2;
    const int tig  = lane & 3;
    const int r0   = wid * 16;
    const size_t p0 = (size_t)blockIdx.x * 128;

    const uint32_t lrow  = lane & 15;
    const uint32_t lhi16 = ((lane >> 4) & 1) * 16;
    const uint32_t brow  = (lane & 7) + ((lane >> 4) << 3);
    const uint32_t bhi16 = ((lane >> 3) & 1) * 16;

    const uint32_t As  = (uint32_t)__cvta_generic_to_shared(A32);
    const uint32_t Hs  = (uint32_t)__cvta_generic_to_shared(H32);
    const uint32_t W1base = (uint32_t)__cvta_generic_to_shared(smu + W1_O);
    const uint32_t W2base = (uint32_t)__cvta_generic_to_shared(smu + W2_O);
    const uint32_t w1buf[2] = {W1base, W1base + 64*52*4};
    const uint32_t w2buf[2] = {W2base, W2base + 96*36*4};

    // stage chunk c weights into buffer bufi (w1: 768 uint4, w2: 768 uint4)
    auto stage_chunk = [&](int c, int bufi) {
        const uint4* s1p = g_w1p4 + c*(64*48/4);
#pragma unroll
        for (int i = 0; i < 3; i++) {
            const int e = t + 256*i;              // e < 768
            const int n = e / 12, q = e - 12*n;
            cp_async16(w1buf[bufi] + (n*52 + 4*q)*4, s1p + e);
        }
        const uint4* s2p = g_w2p4 + c*(96*32/4);
#pragma unroll
        for (int i = 0; i < 3; i++) {
            const int e = t + 256*i;              // e < 768
            const int n = e >> 3, q = e & 7;
            cp_async16(w2buf[bufi] + (n*36 + 4*q)*4, s2p + e);
        }
    };

    // kick off first chunk fetch before LN2
    stage_chunk(0, 0);
    CP_COMMIT();

    for (int i = t; i < 384; i += 256) sb1[i] = b1[i];
    if (t < 96) sb2[t] = b2[t];

    {
        const int row = t >> 1, q = t & 1;
        const float* xr = g_x1 + (p0 + row)*96 + q*48;
        float v[48];
        float s1 = 0.f, s2 = 0.f;
#pragma unroll
        for (int k = 0; k < 12; k++) {
            float4 f = ((const float4*)xr)[k];
            v[4*k+0]=f.x; v[4*k+1]=f.y; v[4*k+2]=f.z; v[4*k+3]=f.w;
            s1 += f.x+f.y+f.z+f.w;
            s2 += f.x*f.x+f.y*f.y+f.z*f.z+f.w*f.w;
        }
        s1 += __shfl_xor_sync(0xffffffffu, s1, 1);
        s2 += __shfl_xor_sync(0xffffffffu, s2, 1);
        const float mean = s1 * (1.f/96.f);
        const float var  = s2 * (1.f/96.f) - mean*mean;
        const float rstd = rsqrtf(var + 1e-5f);
#pragma unroll
        for (int k = 0; k < 24; k++) {
            const int c = q*48 + 2*k;
            float a0 = (v[2*k]   - mean)*rstd*n2g[c]   + n2b[c];
            float a1 = (v[2*k+1] - mean)*rstd*n2g[c+1] + n2b[c+1];
            A32[row*52 + q*24 + k] = pack_bf16(a0, a1);
        }
    }

    float d2[12][4];
#pragma unroll
    for (int nt = 0; nt < 12; nt++)
#pragma unroll
        for (int i = 0; i < 4; i++) d2[nt][i] = 0.f;

    for (int c = 0; c < 6; c++) {
        const int co0 = c*64;
        CP_WAIT0();
        __syncthreads();   // weights(c) + A32 (c==0) visible; old buffer free
        if (c < 5) { stage_chunk(c+1, (c+1) & 1); CP_COMMIT(); }

        const uint32_t W1c = w1buf[c & 1];
        const uint32_t W2c = w2buf[c & 1];

        float d1[8][4];
#pragma unroll
        for (int nt = 0; nt < 8; nt++)
#pragma unroll
            for (int i = 0; i < 4; i++) d1[nt][i] = 0.f;

#pragma unroll
        for (int s = 0; s < 6; s++) {
            uint32_t a0, a1, a2, a3;
            ldsm_x4(a0, a1, a2, a3, As + ((r0+lrow)*52)*4 + lhi16 + s*32);
            const uint32_t bb = W1c + (brow*52)*4 + bhi16 + s*32;
#pragma unroll
            for (int np = 0; np < 4; np++) {
                uint32_t b0, b1, b2, b3;
                ldsm_x4(b0, b1, b2, b3, bb + np*(16*52*4));
                mma_bf16(d1[2*np],   a0, a1, a2, a3, b0, b1);
                mma_bf16(d1[2*np+1], a0, a1, a2, a3, b2, b3);
            }
        }

#pragma unroll
        for (int nt = 0; nt < 8; nt++) {
            const int cn = nt*8 + 2*tig;
            const float bb0 = sb1[co0 + cn], bb1 = sb1[co0 + cn + 1];
            float v0 = d1[nt][0] + bb0, v1 = d1[nt][1] + bb1;
            float v2 = d1[nt][2] + bb0, v3 = d1[nt][3] + bb1;
            v0 = 0.5f*v0*(1.f + erff(v0*0.7071067811865476f));
            v1 = 0.5f*v1*(1.f + erff(v1*0.7071067811865476f));
            v2 = 0.5f*v2*(1.f + erff(v2*0.7071067811865476f));
            v3 = 0.5f*v3*(1.f + erff(v3*0.7071067811865476f));
            H32[(r0+g)*36   + nt*4 + tig] = pack_bf16(v0, v1);
            H32[(r0+g+8)*36 + nt*4 + tig] = pack_bf16(v2, v3);
        }
        __syncwarp();

#pragma unroll
        for (int s = 0; s < 4; s++) {
            uint32_t a0, a1, a2, a3;
            ldsm_x4(a0, a1, a2, a3, Hs + ((r0+lrow)*36)*4 + lhi16 + s*32);
            const uint32_t bb = W2c + (brow*36)*4 + bhi16 + s*32;
#pragma unroll
            for (int np = 0; np < 6; np++) {
                uint32_t b0, b1, b2, b3;
                ldsm_x4(b0, b1, b2, b3, bb + np*(16*36*4));
                mma_bf16(d2[2*np],   a0, a1, a2, a3, b0, b1);
                mma_bf16(d2[2*np+1], a0, a1, a2, a3, b2, b3);
            }
        }
    }

#pragma unroll
    for (int nt = 0; nt < 12; nt++) {
        const int col = nt*8 + 2*tig;
        const float bb0 = sb2[col], bb1 = sb2[col + 1];
        const size_t i0 = (p0 + r0 + g)*96 + col;
        const size_t i1 = (p0 + r0 + g + 8)*96 + col;
        float2 x0 = *(const float2*)(g_x1 + i0);
        float2 x1v = *(const float2*)(g_x1 + i1);
        float2 o0, o1;
        o0.x = x0.x + d2[nt][0] + bb0;
        o0.y = x0.y + d2[nt][1] + bb1;
        o1.x = x1v.x + d2[nt][2] + bb0;
        o1.y = x1v.y + d2[nt][3] + bb1;
        *(float2*)(out + i0) = o0;
        *(float2*)(out + i1) = o1;
    }
}

// ---------------------------------------------------------------------------
extern "C" void kernel_launch(void* const* d_in, const int* in_sizes, int n_in,
                              void* d_out, int out_size)
{
    const float* x    = (const float*)d_in[0];
    const float* n1g  = (const float*)d_in[1];
    const float* n1b  = (const float*)d_in[2];
    const float* qkvw = (const float*)d_in[3];
    const float* qkvb = (const float*)d_in[4];
    const float* relb = (const float*)d_in[5];
    const float* pw   = (const float*)d_in[6];
    const float* pb   = (const float*)d_in[7];
    const float* n2g  = (const float*)d_in[8];
    const float* n2b  = (const float*)d_in[9];
    const float* w1   = (const float*)d_in[10];
    const float* b1   = (const float*)d_in[11];
    const float* w2   = (const float*)d_in[12];
    const float* b2   = (const float*)d_in[13];
    float* out = (float*)d_out;

    cudaFuncSetAttribute(k_attn_mma, cudaFuncAttributeMaxDynamicSharedMemorySize, SMEM_A);
    cudaFuncSetAttribute(k_mlp_mma,  cudaFuncAttributeMaxDynamicSharedMemorySize, SMEM_M);

    k_pack<<<(PACK_N + 255)/256, 256>>>(qkvw, pw, w1, w2);
    k_attn_mma<<<NWIN, 128, SMEM_A>>>(x, n1g, n1b, qkvb, relb, pb);
    k_mlp_mma<<<NPIX/128, 256, SMEM_M>>>(n2g, n2b, b1, b2, out);
}

// round 15
// speedup vs baseline: 6.3667x; 1.1485x over previous
#include <cuda_runtime.h>
#include <cuda_bf16.h>
#include <math.h>
#include <stdint.h>

// Problem constants
#define BB 8
#define HH 256
#define WW2 256
#define CDIM 96
#define NHEAD 4
#define HD 24
#define WS 8
#define NTOK 64
#define SHIFT 4
#define NWIN 8192     // B * 32 * 32
#define NPIX (BB*HH*WW2)

// scratch: x1 = shortcut + attention branch
static __device__ float g_x1[(size_t)BB*HH*WW2*CDIM];

// pre-packed bf16-pair weights, laid out exactly as staged into smem
static __device__ uint4 g_wq4 [3*96*48/4];
static __device__ uint4 g_wp4 [96*48/4];
static __device__ uint4 g_w1p4[6*64*48/4];
static __device__ uint4 g_w2p4[6*96*32/4];

// bf16 mma m16n8k16 (portable PTX, runs on HMMA)
__device__ __forceinline__ void mma_bf16(float* d, uint32_t a0, uint32_t a1,
                                         uint32_t a2, uint32_t a3,
                                         uint32_t b0, uint32_t b1) {
    asm volatile(
        "mma.sync.aligned.m16n8k16.row.col.f32.bf16.bf16.f32 "
        "{%0,%1,%2,%3}, {%4,%5,%6,%7}, {%8,%9}, {%0,%1,%2,%3};"
        : "+f"(d[0]), "+f"(d[1]), "+f"(d[2]), "+f"(d[3])
        : "r"(a0), "r"(a1), "r"(a2), "r"(a3), "r"(b0), "r"(b1));
}

__device__ __forceinline__ void ldsm_x4(uint32_t& r0, uint32_t& r1,
                                        uint32_t& r2, uint32_t& r3, uint32_t saddr) {
    asm volatile("ldmatrix.sync.aligned.m8n8.x4.shared.b16 {%0,%1,%2,%3}, [%4];"
                 : "=r"(r0), "=r"(r1), "=r"(r2), "=r"(r3) : "r"(saddr));
}
__device__ __forceinline__ void ldsm_x2(uint32_t& r0, uint32_t& r1, uint32_t saddr) {
    asm volatile("ldmatrix.sync.aligned.m8n8.x2.shared.b16 {%0,%1}, [%2];"
                 : "=r"(r0), "=r"(r1) : "r"(saddr));
}

__device__ __forceinline__ uint32_t pack_bf16(float lo, float hi) {
    __nv_bfloat162 v = __floats2bfloat162_rn(lo, hi);
    return *(uint32_t*)&v;
}

// cp.async 16B (LDGSTS)
__device__ __forceinline__ void cp_async16(uint32_t saddr, const void* g) {
    asm volatile("cp.async.cg.shared.global [%0], [%1], 16;"
                 :: "r"(saddr), "l"(__cvta_generic_to_global(g)) : "memory");
}
#define CP_COMMIT() asm volatile("cp.async.commit_group;" ::: "memory")
#define CP_WAIT0()  asm volatile("cp.async.wait_group 0;" ::: "memory")

// ===========================================================================
// k_attn_mma smem layout (u32 units). 1 window / block, 256 threads.
// ===========================================================================
#define AQ_SB   0
#define AQ_W    904
#define AQ_A    (AQ_W + 2*96*52)
#define AQ_Q    (AQ_A + 64*52)
#define AQ_K    (AQ_Q + 64*68)
#define AQ_V    (AQ_K + 64*68)
#define SMEM_A_U32 (AQ_V + 96*36)
#define SMEM_A (SMEM_A_U32*4)     // 105504 bytes

// ===========================================================================
// k_mlp_mma smem layout (u32 units). H eliminated (register handoff).
// ===========================================================================
#define SB1_O  0
#define SB2_O  384
#define A_O    512
#define W1_O   (A_O + 128*52)
#define W2_O   (W1_O + 2*64*52)
#define SMEM_M_U32 (W2_O + 2*96*36)
#define SMEM_M (SMEM_M_U32*4)     // 82944 bytes

// ---------------------------------------------------------------------------
// Weight pre-pack kernel (one-time per launch)
// ---------------------------------------------------------------------------
#define PACK_N (13824 + 4608 + 18432 + 18432)
__global__ void k_pack(const float* __restrict__ qkvw, const float* __restrict__ pw,
                       const float* __restrict__ w1,   const float* __restrict__ w2)
{
    int i = blockIdx.x*256 + threadIdx.x;
    if (i < 13824) {                       // qkv: [ch][n][kp]
        const int kp = i % 48, r = i / 48;
        const int ch = r / 96, n = r - 96*ch;
        ((uint32_t*)g_wq4)[i] = pack_bf16(qkvw[(size_t)(2*kp)*288 + ch*96 + n],
                                          qkvw[(size_t)(2*kp+1)*288 + ch*96 + n]);
    } else if (i < 18432) {                // pw: [n][kp]
        const int j = i - 13824;
        const int kp = j % 48, n = j / 48;
        ((uint32_t*)g_wp4)[j] = pack_bf16(pw[(size_t)(2*kp)*96 + n],
                                          pw[(size_t)(2*kp+1)*96 + n]);
    } else if (i < 36864) {                // w1: [c][n][kp]
        const int j = i - 18432;
        const int kp = j % 48, r = j / 48;
        const int c = r / 64, n = r - 64*c;
        ((uint32_t*)g_w1p4)[j] = pack_bf16(w1[(size_t)(2*kp)*384   + c*64 + n],
                                           w1[(size_t)(2*kp+1)*384 + c*64 + n]);
    } else if (i < PACK_N) {               // w2: [c][n][kp]
        const int j = i - 36864;
        const int kp = j % 32, r = j / 32;
        const int c = r / 96, n = r - 96*c;
        ((uint32_t*)g_w2p4)[j] = pack_bf16(w2[(size_t)(c*64+2*kp)*96   + n],
                                           w2[(size_t)(c*64+2*kp+1)*96 + n]);
    }
}

// ---------------------------------------------------------------------------
// Kernel 1 (HMMA): per-window LN1 + shift + QKV + attention + proj + residual
// 256 threads: GEMMs -> warp = (m-tile, n-half); attention -> warp = (head, m-half)
// ---------------------------------------------------------------------------
__global__ __launch_bounds__(256, 2) void k_attn_mma(
    const float* __restrict__ x,
    const float* __restrict__ n1g, const float* __restrict__ n1b,
    const float* __restrict__ qkvb,
    const float* __restrict__ relb,
    const float* __restrict__ pb)
{
    extern __shared__ uint32_t smu[];
    float*    sbias = (float*)(smu + AQ_SB);
    uint32_t* A32 = smu + AQ_A;   // aliased as O after QKV phase
    uint32_t* Q32 = smu + AQ_Q;
    uint32_t* K32 = smu + AQ_K;
    uint32_t* VT  = smu + AQ_V;

    const int t    = threadIdx.x;
    const int wid  = t >> 5;
    const int lane = t & 31;
    const int g    = lane >> 2;
    const int tig  = lane & 3;
    const int mtA  = wid & 3;      // GEMM m-tile
    const int nh   = wid >> 2;     // GEMM n-half (0/1 -> nt base nh*6)
    const int rG   = mtA * 16;

    const uint32_t lrow  = lane & 15;
    const uint32_t lhi16 = ((lane >> 4) & 1) * 16;
    const uint32_t brow  = (lane & 7) + ((lane >> 4) << 3);
    const uint32_t bhi16 = ((lane >> 3) & 1) * 16;

    const uint32_t As = (uint32_t)__cvta_generic_to_shared(A32);
    const uint32_t Qs = (uint32_t)__cvta_generic_to_shared(Q32);
    const uint32_t Ks = (uint32_t)__cvta_generic_to_shared(K32);
    const uint32_t Vs = (uint32_t)__cvta_generic_to_shared(VT);
    const uint32_t Wb = (uint32_t)__cvta_generic_to_shared(smu + AQ_W);
    const uint32_t wbuf[2] = {Wb, Wb + 96*52*4};

    // staging: 96 rows x 12 uint4, row stride 52 u32 (256 threads)
    auto stage96 = [&](uint32_t dstb, const uint4* src) {
#pragma unroll
        for (int i = 0; i < 5; i++) {
            const int e = t + 256*i;
            if (e < 1152) {
                const int n = e / 12, q = e - 12*n;
                cp_async16(dstb + (n*52 + 4*q)*4, src + e);
            }
        }
    };

    const int win = blockIdx.x;
    const int b   = win >> 10;
    const int wr  = win & 1023;
    const int wh  = wr >> 5;
    const int ww  = wr & 31;
    const bool edgeH = (wh == 31), edgeW = (ww == 31);
    const float SCALE = rsqrtf((float)HD);

    // kick off first weight fetch before doing anything else
    stage96(wbuf[0], g_wq4);
    CP_COMMIT();

    // clipped rel-bias LUT
    for (int e = t; e < 900; e += 256) {
        const int h = e / 225, idx = e - h*225;
        float bv = relb[idx*NHEAD + h];
        sbias[e] = fminf(fmaxf(bv, -5.f), 5.f);
    }
    // zero per-head k-pad pairs (12..15) in Q32/K32
    for (int i = t; i < 64*16; i += 256) {
        const int row = i >> 4, q = i & 15;
        const int idx = row*68 + (q >> 2)*16 + 12 + (q & 3);
        Q32[idx] = 0; K32[idx] = 0;
    }

    // ---- LN1 with cyclic-shift gather -> A32 bf16 (4 threads/row) ----
    {
        const int row = t >> 2, q = t & 3;
        const int i = row >> 3, j = row & 7;
        const int h0 = (wh*8 + i + SHIFT) & 255;
        const int w0 = (ww*8 + j + SHIFT) & 255;
        const float* xr = x + (((size_t)b*HH + h0)*WW2 + w0)*CDIM + q*24;
        float v[24];
        float s1 = 0.f, s2 = 0.f;
#pragma unroll
        for (int k = 0; k < 6; k++) {
            float4 f = ((const float4*)xr)[k];
            v[4*k+0]=f.x; v[4*k+1]=f.y; v[4*k+2]=f.z; v[4*k+3]=f.w;
            s1 += f.x+f.y+f.z+f.w;
            s2 += f.x*f.x+f.y*f.y+f.z*f.z+f.w*f.w;
        }
        s1 += __shfl_xor_sync(0xffffffffu, s1, 1);
        s2 += __shfl_xor_sync(0xffffffffu, s2, 1);
        s1 += __shfl_xor_sync(0xffffffffu, s1, 2);
        s2 += __shfl_xor_sync(0xffffffffu, s2, 2);
        const float mean = s1 * (1.f/96.f);
        const float var  = s2 * (1.f/96.f) - mean*mean;
        const float rstd = rsqrtf(var + 1e-5f);
#pragma unroll
        for (int k = 0; k < 12; k++) {
            const int c = q*24 + 2*k;
            float a0 = (v[2*k]   - mean)*rstd*n1g[c]   + n1b[c];
            float a1 = (v[2*k+1] - mean)*rstd*n1g[c+1] + n1b[c+1];
            A32[row*52 + q*12 + k] = pack_bf16(a0, a1);
        }
    }

    // ---- QKV: 3 chunk GEMMs; each warp: 1 m-tile x 6 n-tiles ----
    for (int ch = 0; ch < 3; ch++) {
        CP_WAIT0();
        __syncthreads();
        if (ch < 2) stage96(wbuf[(ch+1)&1], g_wq4 + (ch+1)*(96*48/4));
        else        stage96(wbuf[1], g_wp4);     // proj weights, hidden under attention
        CP_COMMIT();

        const uint32_t Wcur = wbuf[ch & 1];
        float d1[6][4];
#pragma unroll
        for (int nt = 0; nt < 6; nt++)
#pragma unroll
            for (int i = 0; i < 4; i++) d1[nt][i] = 0.f;
#pragma unroll
        for (int s = 0; s < 6; s++) {
            uint32_t a0, a1, a2, a3;
            ldsm_x4(a0, a1, a2, a3, As + ((rG+lrow)*52)*4 + lhi16 + s*32);
            const uint32_t bb = Wcur + ((nh*48 + brow)*52)*4 + bhi16 + s*32;
#pragma unroll
            for (int np = 0; np < 3; np++) {
                uint32_t b0, b1, b2, b3;
                ldsm_x4(b0, b1, b2, b3, bb + np*(16*52*4));
                mma_bf16(d1[2*np],   a0, a1, a2, a3, b0, b1);
                mma_bf16(d1[2*np+1], a0, a1, a2, a3, b2, b3);
            }
        }

        const int c0 = ch * 96;
        if (ch < 2) {
            uint32_t* DST = (ch == 0) ? Q32 : K32;
            const float scl = (ch == 0) ? SCALE : 1.f;
#pragma unroll
            for (int nt = 0; nt < 6; nt++) {
                const int c = (nh*6 + nt)*8 + 2*tig;
                const int h = c / 24, dd = c - 24*h;
                const float bb0 = __ldg(qkvb + c0 + c), bb1 = __ldg(qkvb + c0 + c + 1);
                DST[(rG+g)*68   + h*16 + (dd>>1)] =
                    pack_bf16((d1[nt][0]+bb0)*scl, (d1[nt][1]+bb1)*scl);
                DST[(rG+g+8)*68 + h*16 + (dd>>1)] =
                    pack_bf16((d1[nt][2]+bb0)*scl, (d1[nt][3]+bb1)*scl);
            }
        } else {
            // V transposed: VT[c][token]
#pragma unroll
            for (int nt = 0; nt < 6; nt++) {
                const int c = (nh*6 + nt)*8 + 2*tig;
                const float bb0 = __ldg(qkvb + c0 + c), bb1 = __ldg(qkvb + c0 + c + 1);
                __nv_bfloat16* v0p = (__nv_bfloat16*)(VT + (size_t)c*36);
                __nv_bfloat16* v1p = (__nv_bfloat16*)(VT + (size_t)(c+1)*36);
                v0p[rG+g]   = __float2bfloat16(d1[nt][0] + bb0);
                v1p[rG+g]   = __float2bfloat16(d1[nt][1] + bb1);
                v0p[rG+g+8] = __float2bfloat16(d1[nt][2] + bb0);
                v1p[rG+g+8] = __float2bfloat16(d1[nt][3] + bb1);
            }
        }
    }
    __syncthreads();   // Q/K/VT complete; A32 now dead -> reuse as O

    // ---- attention: warp = (head, m-half), 2 m-tiles each ----
    {
        const int h  = wid & 3;
        const int mh = wid >> 2;
#pragma unroll
        for (int mi = 0; mi < 2; mi++) {
            const int rA = (2*mh + mi)*16;
            float d[8][4];
#pragma unroll
            for (int nt = 0; nt < 8; nt++)
#pragma unroll
                for (int i = 0; i < 4; i++) d[nt][i] = 0.f;

            // scores = Q @ K^T  (2 k-steps; pads are zero)
#pragma unroll
            for (int s = 0; s < 2; s++) {
                uint32_t a0, a1, a2, a3;
                ldsm_x4(a0, a1, a2, a3,
                        Qs + ((rA+lrow)*68)*4 + h*64 + lhi16 + s*32);
                const uint32_t bb = Ks + (brow*68)*4 + h*64 + bhi16 + s*32;
#pragma unroll
                for (int np = 0; np < 4; np++) {
                    uint32_t b0, b1, b2, b3;
                    ldsm_x4(b0, b1, b2, b3, bb + np*(16*68*4));
                    mma_bf16(d[2*np],   a0, a1, a2, a3, b0, b1);
                    mma_bf16(d[2*np+1], a0, a1, a2, a3, b2, b3);
                }
            }

            // mask + bias + clip
            const int n1a = rA + g, n1b2 = rA + g + 8;
            const int i1a = n1a >> 3, j1a = n1a & 7;
            const int i1b = n1b2 >> 3, j1b = n1b2 & 7;
            const int r1a = (edgeH ? ((i1a < 4) ? 1 : 2) : 0)*3 + (edgeW ? ((j1a < 4) ? 1 : 2) : 0);
            const int r1b = (edgeH ? ((i1b < 4) ? 1 : 2) : 0)*3 + (edgeW ? ((j1b < 4) ? 1 : 2) : 0);
#pragma unroll
            for (int nt = 0; nt < 8; nt++) {
#pragma unroll
                for (int e = 0; e < 2; e++) {
                    const int cc = nt*8 + 2*tig + e;
                    const int i2 = cc >> 3, j2 = cc & 7;
                    const int r2 = (edgeH ? ((i2 < 4) ? 1 : 2) : 0)*3 + (edgeW ? ((j2 < 4) ? 1 : 2) : 0);
                    const float ba = sbias[h*225 + (i1a-i2+7)*15 + (j1a-j2+7)];
                    const float bbv = sbias[h*225 + (i1b-i2+7)*15 + (j1b-j2+7)];
                    float va = d[nt][e]   + ((r1a == r2) ? 0.f : -1e9f) + ba;
                    float vb = d[nt][e+2] + ((r1b == r2) ? 0.f : -1e9f) + bbv;
                    d[nt][e]   = fminf(fmaxf(va, -10.f), 10.f);
                    d[nt][e+2] = fminf(fmaxf(vb, -10.f), 10.f);
                }
            }

            // softmax (rows g and g+8, reduced over tig quad)
            float mx0 = -1e30f, mx1 = -1e30f;
#pragma unroll
            for (int nt = 0; nt < 8; nt++) {
                mx0 = fmaxf(mx0, fmaxf(d[nt][0], d[nt][1]));
                mx1 = fmaxf(mx1, fmaxf(d[nt][2], d[nt][3]));
            }
            mx0 = fmaxf(mx0, __shfl_xor_sync(0xffffffffu, mx0, 1));
            mx1 = fmaxf(mx1, __shfl_xor_sync(0xffffffffu, mx1, 1));
            mx0 = fmaxf(mx0, __shfl_xor_sync(0xffffffffu, mx0, 2));
            mx1 = fmaxf(mx1, __shfl_xor_sync(0xffffffffu, mx1, 2));
            float sm0 = 0.f, sm1 = 0.f;
#pragma unroll
            for (int nt = 0; nt < 8; nt++) {
                d[nt][0] = __expf(d[nt][0] - mx0); sm0 += d[nt][0];
                d[nt][1] = __expf(d[nt][1] - mx0); sm0 += d[nt][1];
                d[nt][2] = __expf(d[nt][2] - mx1); sm1 += d[nt][2];
                d[nt][3] = __expf(d[nt][3] - mx1); sm1 += d[nt][3];
            }
            sm0 += __shfl_xor_sync(0xffffffffu, sm0, 1);
            sm1 += __shfl_xor_sync(0xffffffffu, sm1, 1);
            sm0 += __shfl_xor_sync(0xffffffffu, sm0, 2);
            sm1 += __shfl_xor_sync(0xffffffffu, sm1, 2);
            const float inv0 = 1.f / sm0, inv1 = 1.f / sm1;
#pragma unroll
            for (int nt = 0; nt < 8; nt++) {
                d[nt][0] *= inv0; d[nt][1] *= inv0;
                d[nt][2] *= inv1; d[nt][3] *= inv1;
            }

            // AV: P (regs -> A frags) @ VT
            float oacc[3][4];
#pragma unroll
            for (int vt = 0; vt < 3; vt++)
#pragma unroll
                for (int i = 0; i < 4; i++) oacc[vt][i] = 0.f;
#pragma unroll
            for (int s = 0; s < 4; s++) {
                uint32_t a0 = pack_bf16(d[2*s][0],   d[2*s][1]);
                uint32_t a1 = pack_bf16(d[2*s][2],   d[2*s][3]);
                uint32_t a2 = pack_bf16(d[2*s+1][0], d[2*s+1][1]);
                uint32_t a3 = pack_bf16(d[2*s+1][2], d[2*s+1][3]);
                {
                    uint32_t b0, b1, b2, b3;
                    ldsm_x4(b0, b1, b2, b3,
                            Vs + ((h*24 + brow)*36)*4 + bhi16 + s*32);
                    mma_bf16(oacc[0], a0, a1, a2, a3, b0, b1);
                    mma_bf16(oacc[1], a0, a1, a2, a3, b2, b3);
                }
                {
                    uint32_t b0, b1;
                    ldsm_x2(b0, b1,
                            Vs + ((h*24 + 16 + (lane & 7))*36)*4 + bhi16 + s*32);
                    mma_bf16(oacc[2], a0, a1, a2, a3, b0, b1);
                }
            }
            // write O (aliases A32): col = h*24 + vt*8 + 2tig
#pragma unroll
            for (int vt = 0; vt < 3; vt++) {
                const int pi = h*12 + vt*4 + tig;
                A32[(rA+g)*52   + pi] = pack_bf16(oacc[vt][0], oacc[vt][1]);
                A32[(rA+g+8)*52 + pi] = pack_bf16(oacc[vt][2], oacc[vt][3]);
            }
        }
    }
    CP_WAIT0();        // proj weights landed long ago
    __syncthreads();   // O complete + proj weights visible

    // ---- proj: O[64x96] @ pw^T + un-shift residual -> g_x1 ----
    {
        const uint32_t Wcur = wbuf[1];
        float d2[6][4];
#pragma unroll
        for (int nt = 0; nt < 6; nt++)
#pragma unroll
            for (int i = 0; i < 4; i++) d2[nt][i] = 0.f;
#pragma unroll
        for (int s = 0; s < 6; s++) {
            uint32_t a0, a1, a2, a3;
            ldsm_x4(a0, a1, a2, a3, As + ((rG+lrow)*52)*4 + lhi16 + s*32);
            const uint32_t bb = Wcur + ((nh*48 + brow)*52)*4 + bhi16 + s*32;
#pragma unroll
            for (int np = 0; np < 3; np++) {
                uint32_t b0, b1, b2, b3;
                ldsm_x4(b0, b1, b2, b3, bb + np*(16*52*4));
                mma_bf16(d2[2*np],   a0, a1, a2, a3, b0, b1);
                mma_bf16(d2[2*np+1], a0, a1, a2, a3, b2, b3);
            }
        }
        // epilogue: un-shift + residual
        const int ra = rG + g, rb2 = rG + g + 8;
        const int ia = ra >> 3, ja = ra & 7;
        const int ib = rb2 >> 3, jb = rb2 & 7;
        const size_t basea = (((size_t)b*HH + ((wh*8 + ia + SHIFT) & 255))*WW2
                              + ((ww*8 + ja + SHIFT) & 255))*CDIM;
        const size_t baseb = (((size_t)b*HH + ((wh*8 + ib + SHIFT) & 255))*WW2
                              + ((ww*8 + jb + SHIFT) & 255))*CDIM;
#pragma unroll
        for (int nt = 0; nt < 6; nt++) {
            const int c = (nh*6 + nt)*8 + 2*tig;
            const float p0v = __ldg(pb + c), p1v = __ldg(pb + c + 1);
            float2 xa = *(const float2*)(x + basea + c);
            float2 xb = *(const float2*)(x + baseb + c);
            float2 oa, ob;
            oa.x = xa.x + d2[nt][0] + p0v;
            oa.y = xa.y + d2[nt][1] + p1v;
            ob.x = xb.x + d2[nt][2] + p0v;
            ob.y = xb.y + d2[nt][3] + p1v;
            *(float2*)(g_x1 + basea + c) = oa;
            *(float2*)(g_x1 + baseb + c) = ob;
        }
    }
}

// ---------------------------------------------------------------------------
// Kernel 2 (HMMA): 128 pixels/block  LN2 + MLP + residual
// H never touches smem: GEMM1 D-frags -> GELU in regs -> GEMM2 A-frags
// ---------------------------------------------------------------------------
__global__ __launch_bounds__(256, 2) void k_mlp_mma(
    const float* __restrict__ n2g, const float* __restrict__ n2b,
    const float* __restrict__ b1,  const float* __restrict__ b2,
    float* __restrict__ out)
{
    extern __shared__ uint32_t smu[];
    float*    sb1 = (float*)(smu + SB1_O);
    float*    sb2 = (float*)(smu + SB2_O);
    uint32_t* A32 = smu + A_O;

    const int t    = threadIdx.x;
    const int wid  = t >> 5;
    const int lane = t & 31;
    const int g    = lane >> 2;
    const int tig  = lane & 3;
    const int r0   = wid * 16;
    const size_t p0 = (size_t)blockIdx.x * 128;

    const uint32_t lrow  = lane & 15;
    const uint32_t lhi16 = ((lane >> 4) & 1) * 16;
    const uint32_t brow  = (lane & 7) + ((lane >> 4) << 3);
    const uint32_t bhi16 = ((lane >> 3) & 1) * 16;

    const uint32_t As  = (uint32_t)__cvta_generic_to_shared(A32);
    const uint32_t W1base = (uint32_t)__cvta_generic_to_shared(smu + W1_O);
    const uint32_t W2base = (uint32_t)__cvta_generic_to_shared(smu + W2_O);
    const uint32_t w1buf[2] = {W1base, W1base + 64*52*4};
    const uint32_t w2buf[2] = {W2base, W2base + 96*36*4};

    auto stage_chunk = [&](int c, int bufi) {
        const uint4* s1p = g_w1p4 + c*(64*48/4);
#pragma unroll
        for (int i = 0; i < 3; i++) {
            const int e = t + 256*i;              // e < 768
            const int n = e / 12, q = e - 12*n;
            cp_async16(w1buf[bufi] + (n*52 + 4*q)*4, s1p + e);
        }
        const uint4* s2p = g_w2p4 + c*(96*32/4);
#pragma unroll
        for (int i = 0; i < 3; i++) {
            const int e = t + 256*i;              // e < 768
            const int n = e >> 3, q = e & 7;
            cp_async16(w2buf[bufi] + (n*36 + 4*q)*4, s2p + e);
        }
    };

    stage_chunk(0, 0);
    CP_COMMIT();

    for (int i = t; i < 384; i += 256) sb1[i] = b1[i];
    if (t < 96) sb2[t] = b2[t];

    {
        const int row = t >> 1, q = t & 1;
        const float* xr = g_x1 + (p0 + row)*96 + q*48;
        float v[48];
        float s1 = 0.f, s2 = 0.f;
#pragma unroll
        for (int k = 0; k < 12; k++) {
            float4 f = ((const float4*)xr)[k];
            v[4*k+0]=f.x; v[4*k+1]=f.y; v[4*k+2]=f.z; v[4*k+3]=f.w;
            s1 += f.x+f.y+f.z+f.w;
            s2 += f.x*f.x+f.y*f.y+f.z*f.z+f.w*f.w;
        }
        s1 += __shfl_xor_sync(0xffffffffu, s1, 1);
        s2 += __shfl_xor_sync(0xffffffffu, s2, 1);
        const float mean = s1 * (1.f/96.f);
        const float var  = s2 * (1.f/96.f) - mean*mean;
        const float rstd = rsqrtf(var + 1e-5f);
#pragma unroll
        for (int k = 0; k < 24; k++) {
            const int c = q*48 + 2*k;
            float a0 = (v[2*k]   - mean)*rstd*n2g[c]   + n2b[c];
            float a1 = (v[2*k+1] - mean)*rstd*n2g[c+1] + n2b[c+1];
            A32[row*52 + q*24 + k] = pack_bf16(a0, a1);
        }
    }

    float d2[12][4];
#pragma unroll
    for (int nt = 0; nt < 12; nt++)
#pragma unroll
        for (int i = 0; i < 4; i++) d2[nt][i] = 0.f;

    for (int c = 0; c < 6; c++) {
        const int co0 = c*64;
        CP_WAIT0();
        __syncthreads();   // weights(c) + A32 (c==0) visible; old buffer free
        if (c < 5) { stage_chunk(c+1, (c+1) & 1); CP_COMMIT(); }

        const uint32_t W1c = w1buf[c & 1];
        const uint32_t W2c = w2buf[c & 1];

        // ---- GEMM1: d1[16x64] = A @ W1c^T ----
        float d1[8][4];
#pragma unroll
        for (int nt = 0; nt < 8; nt++)
#pragma unroll
            for (int i = 0; i < 4; i++) d1[nt][i] = 0.f;

#pragma unroll
        for (int s = 0; s < 6; s++) {
            uint32_t a0, a1, a2, a3;
            ldsm_x4(a0, a1, a2, a3, As + ((r0+lrow)*52)*4 + lhi16 + s*32);
            const uint32_t bb = W1c + (brow*52)*4 + bhi16 + s*32;
#pragma unroll
            for (int np = 0; np < 4; np++) {
                uint32_t b0, b1, b2, b3;
                ldsm_x4(b0, b1, b2, b3, bb + np*(16*52*4));
                mma_bf16(d1[2*np],   a0, a1, a2, a3, b0, b1);
                mma_bf16(d1[2*np+1], a0, a1, a2, a3, b2, b3);
            }
        }

        // ---- +b1, GELU in registers ----
#pragma unroll
        for (int nt = 0; nt < 8; nt++) {
            const int cn = nt*8 + 2*tig;
            const float bb0 = sb1[co0 + cn], bb1 = sb1[co0 + cn + 1];
            float v0 = d1[nt][0] + bb0, v1 = d1[nt][1] + bb1;
            float v2 = d1[nt][2] + bb0, v3 = d1[nt][3] + bb1;
            d1[nt][0] = 0.5f*v0*(1.f + erff(v0*0.7071067811865476f));
            d1[nt][1] = 0.5f*v1*(1.f + erff(v1*0.7071067811865476f));
            d1[nt][2] = 0.5f*v2*(1.f + erff(v2*0.7071067811865476f));
            d1[nt][3] = 0.5f*v3*(1.f + erff(v3*0.7071067811865476f));
        }

        // ---- GEMM2: d2 += H @ W2c^T, H fed straight from d1 regs ----
#pragma unroll
        for (int s = 0; s < 4; s++) {
            uint32_t a0 = pack_bf16(d1[2*s][0],   d1[2*s][1]);
            uint32_t a1 = pack_bf16(d1[2*s][2],   d1[2*s][3]);
            uint32_t a2 = pack_bf16(d1[2*s+1][0], d1[2*s+1][1]);
            uint32_t a3 = pack_bf16(d1[2*s+1][2], d1[2*s+1][3]);
            const uint32_t bb = W2c + (brow*36)*4 + bhi16 + s*32;
#pragma unroll
            for (int np = 0; np < 6; np++) {
                uint32_t b0, b1, b2, b3;
                ldsm_x4(b0, b1, b2, b3, bb + np*(16*36*4));
                mma_bf16(d2[2*np],   a0, a1, a2, a3, b0, b1);
                mma_bf16(d2[2*np+1], a0, a1, a2, a3, b2, b3);
            }
        }
    }

#pragma unroll
    for (int nt = 0; nt < 12; nt++) {
        const int col = nt*8 + 2*tig;
        const float bb0 = sb2[col], bb1 = sb2[col + 1];
        const size_t i0 = (p0 + r0 + g)*96 + col;
        const size_t i1 = (p0 + r0 + g + 8)*96 + col;
        float2 x0 = *(const float2*)(g_x1 + i0);
        float2 x1v = *(const float2*)(g_x1 + i1);
        float2 o0, o1;
        o0.x = x0.x + d2[nt][0] + bb0;
        o0.y = x0.y + d2[nt][1] + bb1;
        o1.x = x1v.x + d2[nt][2] + bb0;
        o1.y = x1v.y + d2[nt][3] + bb1;
        *(float2*)(out + i0) = o0;
        *(float2*)(out + i1) = o1;
    }
}

// ---------------------------------------------------------------------------
extern "C" void kernel_launch(void* const* d_in, const int* in_sizes, int n_in,
                              void* d_out, int out_size)
{
    const float* x    = (const float*)d_in[0];
    const float* n1g  = (const float*)d_in[1];
    const float* n1b  = (const float*)d_in[2];
    const float* qkvw = (const float*)d_in[3];
    const float* qkvb = (const float*)d_in[4];
    const float* relb = (const float*)d_in[5];
    const float* pw   = (const float*)d_in[6];
    const float* pb   = (const float*)d_in[7];
    const float* n2g  = (const float*)d_in[8];
    const float* n2b  = (const float*)d_in[9];
    const float* w1   = (const float*)d_in[10];
    const float* b1   = (const float*)d_in[11];
    const float* w2   = (const float*)d_in[12];
    const float* b2   = (const float*)d_in[13];
    float* out = (float*)d_out;

    cudaFuncSetAttribute(k_attn_mma, cudaFuncAttributeMaxDynamicSharedMemorySize, SMEM_A);
    cudaFuncSetAttribute(k_mlp_mma,  cudaFuncAttributeMaxDynamicSharedMemorySize, SMEM_M);

    k_pack<<<(PACK_N + 255)/256, 256>>>(qkvw, pw, w1, w2);
    k_attn_mma<<<NWIN, 256, SMEM_A>>>(x, n1g, n1b, qkvb, relb, pb);
    k_mlp_mma<<<NPIX/128, 256, SMEM_M>>>(n2g, n2b, b1, b2, out);
}